// round 7
// baseline (speedup 1.0000x reference)
#include <cuda_runtime.h>
#include <cuda_bf16.h>
#include <math.h>
#include <stdint.h>

#define Bz  64
#define Sz  512
#define INz 512
#define Hz  1024
#define G3z 3072
#define NBLK 128

// ---------------- scratch (device globals; no allocation allowed) ----------------
__device__ float g_gi0[(size_t)2 * Bz * Sz * G3z];   // [dir][b][s][n]
__device__ float g_gi1[(size_t)2 * Sz * Bz * G3z];   // [dir][s][b][n]
__device__ float g_h0 [(size_t)2 * Sz * Bz * Hz];    // fp32 h0 for recurrence use
__device__ float g_h1 [(size_t)2 * 2 * Bz * Hz];     // ping-pong [buf][dir][b][j]
__device__ float g_b0 [2 * G3z];
__device__ unsigned g_count;
__device__ unsigned g_phase;

// pre-split bf16 operands for the HMMA GEMMs
__device__ __align__(16) __nv_bfloat16 g_xhi [(size_t)Bz * Sz * INz];
__device__ __align__(16) __nv_bfloat16 g_xlo [(size_t)Bz * Sz * INz];
__device__ __align__(16) __nv_bfloat16 g_W0hi[(size_t)2 * G3z * INz];
__device__ __align__(16) __nv_bfloat16 g_W0lo[(size_t)2 * G3z * INz];
__device__ __align__(16) __nv_bfloat16 g_W1hi[(size_t)2 * G3z * Hz];
__device__ __align__(16) __nv_bfloat16 g_W1lo[(size_t)2 * G3z * Hz];
__device__ __align__(16) __nv_bfloat16 g_h0hi[(size_t)2 * Sz * Bz * Hz];
__device__ __align__(16) __nv_bfloat16 g_h0lo[(size_t)2 * Sz * Bz * Hz];

__device__ __forceinline__ uint32_t smem_u32(const void* p) {
    uint32_t a;
    asm("{ .reg .u64 t; cvta.to.shared.u64 t, %1; cvt.u32.u64 %0, t; }" : "=r"(a) : "l"(p));
    return a;
}

__device__ __forceinline__ void split_bf16(float v, __nv_bfloat16& hi, __nv_bfloat16& lo) {
    hi = __float2bfloat16(v);
    lo = __float2bfloat16(v - __bfloat162float(hi));
}

// ---------------- grid barrier (release/acquire, monotonic phase) -----------------
__device__ __forceinline__ void grid_barrier(unsigned target)
{
    __syncthreads();
    if (threadIdx.x == 0) {
        unsigned old;
        asm volatile("atom.release.gpu.add.u32 %0, [%1], 1;"
                     : "=r"(old) : "l"(&g_count) : "memory");
        if (old == NBLK - 1) {
            g_count = 0;
            asm volatile("red.release.gpu.add.u32 [%0], 1;"
                         :: "l"(&g_phase) : "memory");
        } else {
            unsigned v;
            do {
                asm volatile("ld.acquire.gpu.u32 %0, [%1];"
                             : "=r"(v) : "l"(&g_phase) : "memory");
            } while (v < target);
        }
    }
    __syncthreads();
}

// ---------------- prep: split/pack operands to bf16 hi/lo -------------------------
__global__ void prep_w0_split(const float* __restrict__ wf, const float* __restrict__ wb,
                              const float* __restrict__ bf, const float* __restrict__ bb)
{
    size_t i = (size_t)blockIdx.x * 256 + threadIdx.x;
    size_t total = (size_t)G3z * INz;
    if (i == 0) { g_count = 0; g_phase = 0; }
    if (i < total) {
        size_t n = i / INz, k = i % INz;
        split_bf16(wf[i], g_W0hi[i], g_W0lo[i]);
        split_bf16(wb[n * INz + (INz - 1 - k)], g_W0hi[total + i], g_W0lo[total + i]);
    }
    if (i < G3z) {
        g_b0[i]       = bf[i];
        g_b0[G3z + i] = bb[i];
    }
}

__global__ void prep_x_split(const float* __restrict__ x)
{
    size_t i = (size_t)blockIdx.x * 256 + threadIdx.x;
    if (i < (size_t)Bz * Sz * INz)
        split_bf16(x[i], g_xhi[i], g_xlo[i]);
}

__global__ void prep_w1_split(const float* __restrict__ wf, const float* __restrict__ wb)
{
    size_t i = (size_t)blockIdx.x * 256 + threadIdx.x;
    size_t total = (size_t)G3z * Hz;
    if (i < total) {
        split_bf16(wf[i], g_W1hi[i], g_W1lo[i]);
        split_bf16(wb[i], g_W1hi[total + i], g_W1lo[total + i]);
    }
}

// ================ HMMA split-bf16 GEMM v2: C = A @ W^T + bias ================
// Operands pre-split in gmem (hi/lo bf16). cp.async producer, 2 CTAs/SM.
// 128x128 tile, K-chunk 32, double-buffered, 8 warps = 2(m) x 4(n), 3 MMA passes.
#define LDSTR 40                            // bf16 per smem row (32 + 8 pad)
#define TILE_BYTES (128 * LDSTR * 2)        // 10240 B per operand tile
#define STAGE_BYTES (4 * TILE_BYTES)        // Ahi, Alo, Bhi, Blo = 40960 B
#define GEMM_SMEM_BYTES (2 * STAGE_BYTES)   // 81920 B

__device__ __forceinline__ void ldm_x4(uint32_t* r, uint32_t addr) {
    asm volatile("ldmatrix.sync.aligned.m8n8.x4.shared.b16 {%0,%1,%2,%3}, [%4];"
                 : "=r"(r[0]), "=r"(r[1]), "=r"(r[2]), "=r"(r[3]) : "r"(addr));
}

__device__ __forceinline__ void mma_16816(float* c, const uint32_t* a, const uint32_t* b) {
    asm volatile(
        "mma.sync.aligned.m16n8k16.row.col.f32.bf16.bf16.f32 "
        "{%0,%1,%2,%3}, {%4,%5,%6,%7}, {%8,%9}, {%0,%1,%2,%3};"
        : "+f"(c[0]), "+f"(c[1]), "+f"(c[2]), "+f"(c[3])
        : "r"(a[0]), "r"(a[1]), "r"(a[2]), "r"(a[3]), "r"(b[0]), "r"(b[1]));
}

__global__ void __launch_bounds__(256, 2) gemm_hmma2(
    const __nv_bfloat16* __restrict__ Ahi, const __nv_bfloat16* __restrict__ Alo, int lda,
    const __nv_bfloat16* __restrict__ Bhi, const __nv_bfloat16* __restrict__ Blo, int ldw,
    const float* __restrict__ bias,
    float* __restrict__ C,
    int K, size_t dirStride, int N0)
{
    extern __shared__ char sm[];
    const int tid = threadIdx.x, lane = tid & 31, wid = tid >> 5;
    const int wm = wid >> 2, wn = wid & 3;
    const int bn = blockIdx.x, bm = blockIdx.y;

    const __nv_bfloat16* Ahi_b = Ahi + (size_t)bm * 128 * lda;
    const __nv_bfloat16* Alo_b = Alo + (size_t)bm * 128 * lda;
    const __nv_bfloat16* Bhi_b = Bhi + (size_t)bn * 128 * ldw;
    const __nv_bfloat16* Blo_b = Blo + (size_t)bn * 128 * ldw;

    float acc[4][4][4];
#pragma unroll
    for (int mi = 0; mi < 4; mi++)
#pragma unroll
        for (int ni = 0; ni < 4; ni++)
#pragma unroll
            for (int e = 0; e < 4; e++) acc[mi][ni][e] = 0.f;

    const int NC = K / 32;
    const uint32_t smb = smem_u32(sm);

    // fragment smem byte addrs (same proven layout as R6)
    const uint32_t a_rowoff = (uint32_t)((wm * 64 + (lane & 15)) * LDSTR + (lane >> 4) * 8) * 2;
    const uint32_t b_rowoff = (uint32_t)((wn * 32 + (lane & 7) + ((lane >> 4) & 1) * 8) * LDSTR
                                         + ((lane >> 3) & 1) * 8) * 2;

    // producer line assignment (fixed per thread/i): 2048 16B-lines per chunk
#define CP_PREFETCH(cc, buf) do {                                             \
        int kt_ = (cc) * 32;                                                  \
        uint32_t stage_ = smb + (uint32_t)(buf) * STAGE_BYTES;                \
        _Pragma("unroll")                                                     \
        for (int i_ = 0; i_ < 8; i_++) {                                      \
            int line_ = tid + 256 * i_;                                       \
            int tile_ = line_ >> 9;                                           \
            int idx_  = line_ & 511;                                          \
            int row_  = idx_ >> 2;                                            \
            int c16_  = idx_ & 3;                                             \
            const __nv_bfloat16* src_;                                        \
            if (tile_ == 0)      src_ = Ahi_b + (size_t)row_ * lda + kt_ + c16_ * 8; \
            else if (tile_ == 1) src_ = Alo_b + (size_t)row_ * lda + kt_ + c16_ * 8; \
            else if (tile_ == 2) src_ = Bhi_b + (size_t)row_ * ldw + kt_ + c16_ * 8; \
            else                 src_ = Blo_b + (size_t)row_ * ldw + kt_ + c16_ * 8; \
            uint32_t dst_ = stage_ + (uint32_t)tile_ * TILE_BYTES             \
                            + (uint32_t)(row_ * (LDSTR * 2) + c16_ * 16);     \
            asm volatile("cp.async.cg.shared.global [%0], [%1], 16;"          \
                         :: "r"(dst_), "l"(src_));                            \
        }                                                                     \
        asm volatile("cp.async.commit_group;" ::: "memory");                  \
    } while (0)

    CP_PREFETCH(0, 0);

    for (int c = 0; c < NC; c++) {
        if (c + 1 < NC) {
            CP_PREFETCH(c + 1, (c + 1) & 1);
            asm volatile("cp.async.wait_group 1;" ::: "memory");
        } else {
            asm volatile("cp.async.wait_group 0;" ::: "memory");
        }
        __syncthreads();

        const uint32_t bufb = smb + (uint32_t)(c & 1) * STAGE_BYTES;
        // passes: (Ahi,Bhi), (Ahi,Blo), (Alo,Bhi)
        const uint32_t aoffs[3] = { 0u, 0u, (uint32_t)TILE_BYTES };
        const uint32_t boffs[3] = { 2u * TILE_BYTES, 3u * TILE_BYTES, 2u * TILE_BYTES };
#pragma unroll
        for (int p = 0; p < 3; p++) {
#pragma unroll
            for (int k16 = 0; k16 < 32; k16 += 16) {
                uint32_t af[4][4], bf[2][4];
#pragma unroll
                for (int mi = 0; mi < 4; mi++)
                    ldm_x4(af[mi], bufb + aoffs[p] + a_rowoff
                                   + (uint32_t)(mi * 16 * LDSTR + k16) * 2);
#pragma unroll
                for (int nj = 0; nj < 2; nj++)
                    ldm_x4(bf[nj], bufb + boffs[p] + b_rowoff
                                   + (uint32_t)(nj * 16 * LDSTR + k16) * 2);
#pragma unroll
                for (int mi = 0; mi < 4; mi++)
#pragma unroll
                    for (int ni = 0; ni < 4; ni++)
                        mma_16816(acc[mi][ni], af[mi], &bf[ni >> 1][(ni & 1) * 2]);
            }
        }
        __syncthreads();
    }
#undef CP_PREFETCH

    // epilogue: add bias, scatter to packed-dir layout
    const int grow = lane >> 2;
    const int gcol = (lane & 3) * 2;
    const int nbase = bn * 128;
    const int dir = nbase / N0;
    const int nn_base = nbase - dir * N0;
    float* Cd = C + (size_t)dir * dirStride;

#pragma unroll
    for (int mi = 0; mi < 4; mi++) {
        size_t m0 = (size_t)bm * 128 + wm * 64 + mi * 16 + grow;
#pragma unroll
        for (int ni = 0; ni < 4; ni++) {
            int nloc = wn * 32 + ni * 8 + gcol;
            float bx = __ldg(&bias[nbase + nloc]);
            float by = __ldg(&bias[nbase + nloc + 1]);
            float2 v0 = make_float2(acc[mi][ni][0] + bx, acc[mi][ni][1] + by);
            float2 v1 = make_float2(acc[mi][ni][2] + bx, acc[mi][ni][3] + by);
            *(float2*)(Cd + m0 * G3z + nn_base + nloc)       = v0;
            *(float2*)(Cd + (m0 + 8) * G3z + nn_base + nloc) = v1;
        }
    }
}

// ---------------- persistent recurrent layer: 512 steps in one kernel -------------
#define SH_W_FLOATS (48 * 1024)
#define SH_X_FLOATS 3136
#define SMEM_BYTES ((SH_W_FLOATS + SH_X_FLOATS) * 4)

__global__ void __launch_bounds__(256) gru_layer_persistent(
    const float* __restrict__ gi_base, size_t gi_dstride, size_t gi_tstride, size_t gi_bstride,
    const float* __restrict__ whf, const float* __restrict__ whb,
    const float* __restrict__ bhf, const float* __restrict__ bhb,
    float* __restrict__ hbuf,
    int mode, unsigned phase_base, float* __restrict__ dout,
    __nv_bfloat16* __restrict__ hhi, __nv_bfloat16* __restrict__ hlo)
{
    extern __shared__ float smemf[];
    float* sh_w = smemf;
    float* sh_x = smemf + SH_W_FLOATS;

    int d  = blockIdx.x >> 6;
    int jg = blockIdx.x & 63;
    int tid = threadIdx.x;
    int q = tid >> 6;
    int r = tid & 63;

    const float* w  = d ? whb : whf;
    const float* bh = d ? bhb : bhf;

    for (int f = tid; f < 48 * 256; f += 256) {
        int row = f >> 8;
        int k4  = (f & 255) * 4;
        int wrow = (row >> 4) * Hz + jg * 16 + (row & 15);
        *(float4*)&sh_w[row * 1024 + k4] = *(const float4*)(w + (size_t)wrow * Hz + k4);
    }
    float bias[12];
#pragma unroll
    for (int c = 0; c < 12; c++) {
        int cg = q * 12 + c;
        bias[c] = __ldg(&bh[(cg >> 4) * Hz + jg * 16 + (cg & 15)]);
    }
    __syncthreads();

    int jj = tid & 15;
    int rb = tid >> 4;
    int jglob = jg * 16 + jj;

    for (int t = 0; t < Sz; t++) {
        if (t > 0) grid_barrier(phase_base + (unsigned)t);

        const float* hp;
        float* ho;
        if (mode == 0) {
            hp = hbuf + ((size_t)d * Sz + (size_t)(t > 0 ? t - 1 : 0)) * Bz * Hz;
            ho = hbuf + ((size_t)d * Sz + t) * Bz * Hz;
        } else {
            int cur = t & 1;
            hp = hbuf + ((size_t)cur * 2 + d) * Bz * Hz;
            ho = hbuf + ((size_t)(cur ^ 1) * 2 + d) * Bz * Hz;
        }
        const float* gi = gi_base + (size_t)d * gi_dstride + (size_t)t * gi_tstride;

        float acc[12];
#pragma unroll
        for (int c = 0; c < 12; c++) acc[c] = 0.f;

        if (t > 0) {
            for (int kt = 0; kt < Hz; kt += 32) {
#pragma unroll
                for (int i = 0; i < 2; i++) {
                    int f = tid * 2 + i;
                    int row = f >> 3;
                    int kq  = (f & 7) * 4;
                    *(float4*)&sh_x[row * 36 + kq] =
                        *(const float4*)(hp + (size_t)row * Hz + kt + kq);
                }
                __syncthreads();
#pragma unroll
                for (int k4 = 0; k4 < 32; k4 += 4) {
                    float4 hv = *(const float4*)&sh_x[r * 36 + k4];
#pragma unroll
                    for (int c = 0; c < 12; c++) {
                        float4 wv = *(const float4*)&sh_w[(q * 12 + c) * 1024 + kt + k4];
                        acc[c] += hv.x * wv.x;
                        acc[c] += hv.y * wv.y;
                        acc[c] += hv.z * wv.z;
                        acc[c] += hv.w * wv.w;
                    }
                }
                __syncthreads();
            }
        }

#pragma unroll
        for (int c = 0; c < 12; c++) acc[c] += bias[c];

#pragma unroll
        for (int c = 0; c < 12; c++) sh_x[(q * 12 + c) * 65 + r] = acc[c];
        __syncthreads();

#pragma unroll
        for (int i = 0; i < 4; i++) {
            int row = rb + 16 * i;
            float ghr = sh_x[(jj)      * 65 + row];
            float ghz = sh_x[(16 + jj) * 65 + row];
            float ghn = sh_x[(32 + jj) * 65 + row];
            size_t gbase = (size_t)row * gi_bstride + jglob;
            float gir = gi[gbase];
            float giz = gi[gbase + Hz];
            float gin = gi[gbase + 2 * Hz];
            float hpv = (t > 0) ? hp[(size_t)row * Hz + jglob] : 0.f;

            float rg = 1.f / (1.f + expf(-(gir + ghr)));
            float zg = 1.f / (1.f + expf(-(giz + ghz)));
            float ng = tanhf(gin + rg * ghn);
            float hnew = (1.f - zg) * ng + zg * hpv;

            ho[(size_t)row * Hz + jglob] = hnew;
            if (mode == 0) {
                // also store bf16 hi/lo for the downstream HMMA GEMM
                size_t off = (((size_t)d * Sz + t) * Bz + row) * Hz + jglob;
                __nv_bfloat16 hb, lb;
                split_bf16(hnew, hb, lb);
                hhi[off] = hb;
                hlo[off] = lb;
            } else {
                dout[((size_t)row * Sz + t) * 2048 + (size_t)d * Hz + jglob] = hnew;
                if (t == Sz - 1)
                    dout[(size_t)Bz * Sz * 2048 + (size_t)row * 2048 + (size_t)d * Hz + jglob] = hnew;
            }
        }
        __syncthreads();
    }
}

// ---------------- host launcher (graph-capturable: 8 kernel nodes) ----------------
extern "C" void kernel_launch(void* const* d_in, const int* in_sizes, int n_in,
                              void* d_out, int out_size)
{
    const float* x      = (const float*)d_in[0];
    const float* w_hh0f = (const float*)d_in[2];
    const float* b_hh0f = (const float*)d_in[4];
    const float* w_hh0b = (const float*)d_in[6];
    const float* b_hh0b = (const float*)d_in[8];
    const float* b_ih1f = (const float*)d_in[11];
    const float* b_hh1f = (const float*)d_in[12];
    const float* w_hh1f = (const float*)d_in[10];
    const float* w_hh1b = (const float*)d_in[14];
    const float* b_ih1b = (const float*)d_in[15];
    const float* b_hh1b = (const float*)d_in[16];
    float* out = (float*)d_out;

    float *gi0, *gi1, *h0, *h1, *b0;
    __nv_bfloat16 *xhi, *xlo, *W0hi, *W0lo, *W1hi, *W1lo, *h0hi, *h0lo;
    cudaGetSymbolAddress((void**)&gi0,  g_gi0);
    cudaGetSymbolAddress((void**)&gi1,  g_gi1);
    cudaGetSymbolAddress((void**)&h0,   g_h0);
    cudaGetSymbolAddress((void**)&h1,   g_h1);
    cudaGetSymbolAddress((void**)&b0,   g_b0);
    cudaGetSymbolAddress((void**)&xhi,  g_xhi);
    cudaGetSymbolAddress((void**)&xlo,  g_xlo);
    cudaGetSymbolAddress((void**)&W0hi, g_W0hi);
    cudaGetSymbolAddress((void**)&W0lo, g_W0lo);
    cudaGetSymbolAddress((void**)&W1hi, g_W1hi);
    cudaGetSymbolAddress((void**)&W1lo, g_W1lo);
    cudaGetSymbolAddress((void**)&h0hi, g_h0hi);
    cudaGetSymbolAddress((void**)&h0lo, g_h0lo);

    cudaFuncSetAttribute(gru_layer_persistent,
                         cudaFuncAttributeMaxDynamicSharedMemorySize, SMEM_BYTES);
    cudaFuncSetAttribute(gemm_hmma2,
                         cudaFuncAttributeMaxDynamicSharedMemorySize, GEMM_SMEM_BYTES);

    // 1) prep: split/pack all GEMM operands to bf16 hi/lo
    prep_w0_split<<<(G3z * INz + 255) / 256, 256>>>(
        (const float*)d_in[1], (const float*)d_in[5],
        (const float*)d_in[3], (const float*)d_in[7]);
    prep_x_split<<<(Bz * Sz * INz + 255) / 256, 256>>>(x);
    prep_w1_split<<<(G3z * Hz + 255) / 256, 256>>>(
        (const float*)d_in[9], (const float*)d_in[13]);

    // 2) gi0 = x @ [W_ih0f ; rev(W_ih0b)]^T + bias
    gemm_hmma2<<<dim3((2 * G3z) / 128, (Bz * Sz) / 128), 256, GEMM_SMEM_BYTES>>>(
        xhi, xlo, INz, W0hi, W0lo, INz, b0, gi0,
        INz, (size_t)Bz * Sz * G3z, G3z);

    // 3) layer-0 recurrence (phases 1..511), writes h0 fp32 + bf16 hi/lo
    gru_layer_persistent<<<NBLK, 256, SMEM_BYTES>>>(
        gi0, (size_t)Bz * Sz * G3z, (size_t)G3z, (size_t)Sz * G3z,
        w_hh0f, w_hh0b, b_hh0f, b_hh0b,
        h0, 0, 0u, nullptr, h0hi, h0lo);

    // 4) gi1 = h0_all @ W_ih1^T + bias (per dir)
    for (int dir = 0; dir < 2; dir++) {
        gemm_hmma2<<<dim3(G3z / 128, (Sz * Bz) / 128), 256, GEMM_SMEM_BYTES>>>(
            h0hi + (size_t)dir * Sz * Bz * Hz,
            h0lo + (size_t)dir * Sz * Bz * Hz, Hz,
            W1hi + (size_t)dir * G3z * Hz,
            W1lo + (size_t)dir * G3z * Hz, Hz,
            dir ? b_ih1b : b_ih1f,
            gi1 + (size_t)dir * Sz * Bz * G3z,
            Hz, (size_t)0, G3z);
    }

    // 5) layer-1 recurrence (phases 512..1022), writes output
    gru_layer_persistent<<<NBLK, 256, SMEM_BYTES>>>(
        gi1, (size_t)Sz * Bz * G3z, (size_t)Bz * G3z, (size_t)G3z,
        w_hh1f, w_hh1b, b_hh1f, b_hh1b,
        h1, 1, (unsigned)(Sz - 1), out, nullptr, nullptr);
}

// round 9
// speedup vs baseline: 2.3866x; 2.3866x over previous
#include <cuda_runtime.h>
#include <cuda_bf16.h>
#include <math.h>
#include <stdint.h>

#define Bz  64
#define Sz  512
#define INz 512
#define Hz  1024
#define G3z 3072
#define NBLK 128

// ---------------- scratch (device globals; no allocation allowed) ----------------
__device__ float g_gi0[(size_t)2 * Bz * Sz * G3z];   // [dir][b][s][n]
__device__ float g_gi1[(size_t)2 * Sz * Bz * G3z];   // [dir][s][b][n]
__device__ float g_b0 [2 * G3z];
__device__ unsigned g_count;
__device__ unsigned g_phase;

// pre-split bf16 operands
__device__ __align__(16) __nv_bfloat16 g_xhi [(size_t)Bz * Sz * INz];
__device__ __align__(16) __nv_bfloat16 g_xlo [(size_t)Bz * Sz * INz];
__device__ __align__(16) __nv_bfloat16 g_W0hi[(size_t)2 * G3z * INz];
__device__ __align__(16) __nv_bfloat16 g_W0lo[(size_t)2 * G3z * INz];
__device__ __align__(16) __nv_bfloat16 g_W1hi[(size_t)2 * G3z * Hz];
__device__ __align__(16) __nv_bfloat16 g_W1lo[(size_t)2 * G3z * Hz];
// hidden state, stored ONLY as bf16 hi/lo
__device__ __align__(16) __nv_bfloat16 g_h0hi[(size_t)2 * Sz * Bz * Hz];
__device__ __align__(16) __nv_bfloat16 g_h0lo[(size_t)2 * Sz * Bz * Hz];
__device__ __align__(16) __nv_bfloat16 g_h1hi[(size_t)2 * 2 * Bz * Hz];
__device__ __align__(16) __nv_bfloat16 g_h1lo[(size_t)2 * 2 * Bz * Hz];

__device__ __forceinline__ uint32_t smem_u32(const void* p) {
    uint32_t a;
    asm("{ .reg .u64 t; cvta.to.shared.u64 t, %1; cvt.u32.u64 %0, t; }" : "=r"(a) : "l"(p));
    return a;
}

__device__ __forceinline__ void split_bf16(float v, __nv_bfloat16& hi, __nv_bfloat16& lo) {
    hi = __float2bfloat16(v);
    lo = __float2bfloat16(v - __bfloat162float(hi));
}

// ---------------- grid barrier (release/acquire, monotonic phase) -----------------
__device__ __forceinline__ void grid_barrier(unsigned target)
{
    __syncthreads();
    if (threadIdx.x == 0) {
        unsigned old;
        asm volatile("atom.release.gpu.add.u32 %0, [%1], 1;"
                     : "=r"(old) : "l"(&g_count) : "memory");
        if (old == NBLK - 1) {
            g_count = 0;
            asm volatile("red.release.gpu.add.u32 [%0], 1;"
                         :: "l"(&g_phase) : "memory");
        } else {
            unsigned v;
            do {
                asm volatile("ld.acquire.gpu.u32 %0, [%1];"
                             : "=r"(v) : "l"(&g_phase) : "memory");
            } while (v < target);
        }
    }
    __syncthreads();
}

// ---------------- prep: split/pack operands to bf16 hi/lo -------------------------
__global__ void prep_w0_split(const float* __restrict__ wf, const float* __restrict__ wb,
                              const float* __restrict__ bf, const float* __restrict__ bb)
{
    size_t i = (size_t)blockIdx.x * 256 + threadIdx.x;
    size_t total = (size_t)G3z * INz;
    if (i == 0) { g_count = 0; g_phase = 0; }
    if (i < total) {
        size_t n = i / INz, k = i % INz;
        split_bf16(wf[i], g_W0hi[i], g_W0lo[i]);
        split_bf16(wb[n * INz + (INz - 1 - k)], g_W0hi[total + i], g_W0lo[total + i]);
    }
    if (i < G3z) {
        g_b0[i]       = bf[i];
        g_b0[G3z + i] = bb[i];
    }
}

__global__ void prep_x_split(const float* __restrict__ x)
{
    size_t i = (size_t)blockIdx.x * 256 + threadIdx.x;
    if (i < (size_t)Bz * Sz * INz)
        split_bf16(x[i], g_xhi[i], g_xlo[i]);
}

__global__ void prep_w1_split(const float* __restrict__ wf, const float* __restrict__ wb)
{
    size_t i = (size_t)blockIdx.x * 256 + threadIdx.x;
    size_t total = (size_t)G3z * Hz;
    if (i < total) {
        split_bf16(wf[i], g_W1hi[i], g_W1lo[i]);
        split_bf16(wb[i], g_W1hi[total + i], g_W1lo[total + i]);
    }
}

// ================ shared HMMA primitives (proven in R6/R7 GEMM) ================
__device__ __forceinline__ void ldm_x4(uint32_t* r, uint32_t addr) {
    asm volatile("ldmatrix.sync.aligned.m8n8.x4.shared.b16 {%0,%1,%2,%3}, [%4];"
                 : "=r"(r[0]), "=r"(r[1]), "=r"(r[2]), "=r"(r[3]) : "r"(addr));
}
__device__ __forceinline__ void ldm_x2(uint32_t* r, uint32_t addr) {
    asm volatile("ldmatrix.sync.aligned.m8n8.x2.shared.b16 {%0,%1}, [%2];"
                 : "=r"(r[0]), "=r"(r[1]) : "r"(addr));
}
__device__ __forceinline__ void mma_16816(float* c, const uint32_t* a, const uint32_t* b) {
    asm volatile(
        "mma.sync.aligned.m16n8k16.row.col.f32.bf16.bf16.f32 "
        "{%0,%1,%2,%3}, {%4,%5,%6,%7}, {%8,%9}, {%0,%1,%2,%3};"
        : "+f"(c[0]), "+f"(c[1]), "+f"(c[2]), "+f"(c[3])
        : "r"(a[0]), "r"(a[1]), "r"(a[2]), "r"(a[3]), "r"(b[0]), "r"(b[1]));
}

// ================ HMMA split-bf16 GEMM: C = A @ W^T + bias (unchanged R7) ======
#define LDSTR 40
#define TILE_BYTES (128 * LDSTR * 2)
#define STAGE_BYTES (4 * TILE_BYTES)
#define GEMM_SMEM_BYTES (2 * STAGE_BYTES)

__global__ void __launch_bounds__(256, 2) gemm_hmma2(
    const __nv_bfloat16* __restrict__ Ahi, const __nv_bfloat16* __restrict__ Alo, int lda,
    const __nv_bfloat16* __restrict__ Bhi, const __nv_bfloat16* __restrict__ Blo, int ldw,
    const float* __restrict__ bias,
    float* __restrict__ C,
    int K, size_t dirStride, int N0)
{
    extern __shared__ char sm[];
    const int tid = threadIdx.x, lane = tid & 31, wid = tid >> 5;
    const int wm = wid >> 2, wn = wid & 3;
    const int bn = blockIdx.x, bm = blockIdx.y;

    const __nv_bfloat16* Ahi_b = Ahi + (size_t)bm * 128 * lda;
    const __nv_bfloat16* Alo_b = Alo + (size_t)bm * 128 * lda;
    const __nv_bfloat16* Bhi_b = Bhi + (size_t)bn * 128 * ldw;
    const __nv_bfloat16* Blo_b = Blo + (size_t)bn * 128 * ldw;

    float acc[4][4][4];
#pragma unroll
    for (int mi = 0; mi < 4; mi++)
#pragma unroll
        for (int ni = 0; ni < 4; ni++)
#pragma unroll
            for (int e = 0; e < 4; e++) acc[mi][ni][e] = 0.f;

    const int NC = K / 32;
    const uint32_t smb = smem_u32(sm);

    const uint32_t a_rowoff = (uint32_t)((wm * 64 + (lane & 15)) * LDSTR + (lane >> 4) * 8) * 2;
    const uint32_t b_rowoff = (uint32_t)((wn * 32 + (lane & 7) + ((lane >> 4) & 1) * 8) * LDSTR
                                         + ((lane >> 3) & 1) * 8) * 2;

#define CP_PREFETCH(cc, buf) do {                                             \
        int kt_ = (cc) * 32;                                                  \
        uint32_t stage_ = smb + (uint32_t)(buf) * STAGE_BYTES;                \
        _Pragma("unroll")                                                     \
        for (int i_ = 0; i_ < 8; i_++) {                                      \
            int line_ = tid + 256 * i_;                                       \
            int tile_ = line_ >> 9;                                           \
            int idx_  = line_ & 511;                                          \
            int row_  = idx_ >> 2;                                            \
            int c16_  = idx_ & 3;                                             \
            const __nv_bfloat16* src_;                                        \
            if (tile_ == 0)      src_ = Ahi_b + (size_t)row_ * lda + kt_ + c16_ * 8; \
            else if (tile_ == 1) src_ = Alo_b + (size_t)row_ * lda + kt_ + c16_ * 8; \
            else if (tile_ == 2) src_ = Bhi_b + (size_t)row_ * ldw + kt_ + c16_ * 8; \
            else                 src_ = Blo_b + (size_t)row_ * ldw + kt_ + c16_ * 8; \
            uint32_t dst_ = stage_ + (uint32_t)tile_ * TILE_BYTES             \
                            + (uint32_t)(row_ * (LDSTR * 2) + c16_ * 16);     \
            asm volatile("cp.async.cg.shared.global [%0], [%1], 16;"          \
                         :: "r"(dst_), "l"(src_));                            \
        }                                                                     \
        asm volatile("cp.async.commit_group;" ::: "memory");                  \
    } while (0)

    CP_PREFETCH(0, 0);

    for (int c = 0; c < NC; c++) {
        if (c + 1 < NC) {
            CP_PREFETCH(c + 1, (c + 1) & 1);
            asm volatile("cp.async.wait_group 1;" ::: "memory");
        } else {
            asm volatile("cp.async.wait_group 0;" ::: "memory");
        }
        __syncthreads();

        const uint32_t bufb = smb + (uint32_t)(c & 1) * STAGE_BYTES;
        const uint32_t aoffs[3] = { 0u, 0u, (uint32_t)TILE_BYTES };
        const uint32_t boffs[3] = { 2u * TILE_BYTES, 3u * TILE_BYTES, 2u * TILE_BYTES };
#pragma unroll
        for (int p = 0; p < 3; p++) {
#pragma unroll
            for (int k16 = 0; k16 < 32; k16 += 16) {
                uint32_t af[4][4], bf[2][4];
#pragma unroll
                for (int mi = 0; mi < 4; mi++)
                    ldm_x4(af[mi], bufb + aoffs[p] + a_rowoff
                                   + (uint32_t)(mi * 16 * LDSTR + k16) * 2);
#pragma unroll
                for (int nj = 0; nj < 2; nj++)
                    ldm_x4(bf[nj], bufb + boffs[p] + b_rowoff
                                   + (uint32_t)(nj * 16 * LDSTR + k16) * 2);
#pragma unroll
                for (int mi = 0; mi < 4; mi++)
#pragma unroll
                    for (int ni = 0; ni < 4; ni++)
                        mma_16816(acc[mi][ni], af[mi], &bf[ni >> 1][(ni & 1) * 2]);
            }
        }
        __syncthreads();
    }
#undef CP_PREFETCH

    const int grow = lane >> 2;
    const int gcol = (lane & 3) * 2;
    const int nbase = bn * 128;
    const int dir = nbase / N0;
    const int nn_base = nbase - dir * N0;
    float* Cd = C + (size_t)dir * dirStride;

#pragma unroll
    for (int mi = 0; mi < 4; mi++) {
        size_t m0 = (size_t)bm * 128 + wm * 64 + mi * 16 + grow;
#pragma unroll
        for (int ni = 0; ni < 4; ni++) {
            int nloc = wn * 32 + ni * 8 + gcol;
            float bx = __ldg(&bias[nbase + nloc]);
            float by = __ldg(&bias[nbase + nloc + 1]);
            float2 v0 = make_float2(acc[mi][ni][0] + bx, acc[mi][ni][1] + by);
            float2 v1 = make_float2(acc[mi][ni][2] + bx, acc[mi][ni][3] + by);
            *(float2*)(Cd + m0 * G3z + nn_base + nloc)       = v0;
            *(float2*)(Cd + (m0 + 8) * G3z + nn_base + nloc) = v1;
        }
    }
}

// ================ persistent HMMA recurrent layer =================================
// 128 CTAs: d = bx>>6, jg = bx&63 (16 H-cols -> 48 gate-cols).
// gh(64x48) = h(64x1024) @ Wslice(48x1024)^T via 3-pass split-bf16 HMMA.
// W slice pre-split in smem (hi/lo, stride LDW). h tiles cp.async double-buffered.
#define LDW  1032                       // bf16 stride, conflict-free ldmatrix
#define WT_BYTES (48 * LDW * 2)         // 99072 per hi/lo
#define HSTR 40                         // bf16 stride for h chunk rows
#define HOP_BYTES (64 * HSTR * 2)       // 5120 per operand
#define HST_BYTES (2 * HOP_BYTES)       // 10240 per stage (hi+lo)
#define REC_SMEM (2 * WT_BYTES + 2 * HST_BYTES)   // 218624

__global__ void __launch_bounds__(256) gru_layer_hmma(
    const float* __restrict__ gi_base, size_t gi_dstride, size_t gi_tstride, size_t gi_bstride,
    const float* __restrict__ whf, const float* __restrict__ whb,
    const float* __restrict__ bhf, const float* __restrict__ bhb,
    __nv_bfloat16* __restrict__ hhi, __nv_bfloat16* __restrict__ hlo,
    int mode, unsigned phase_base, float* __restrict__ dout)
{
    extern __shared__ char sm[];
    __nv_bfloat16* Whi = (__nv_bfloat16*)sm;
    __nv_bfloat16* Wlo = (__nv_bfloat16*)(sm + WT_BYTES);
    float* shg = (float*)(sm + 2 * WT_BYTES);        // aliases h stages (used post-MMA)
    const uint32_t whis = smem_u32(Whi);
    const uint32_t wlos = smem_u32(Wlo);
    const uint32_t hsm  = smem_u32(sm + 2 * WT_BYTES);

    const int d  = blockIdx.x >> 6;
    const int jg = blockIdx.x & 63;
    const int tid = threadIdx.x, lane = tid & 31, wid = tid >> 5;
    const int wm = wid & 3, wn = wid >> 2;           // 4m x 2n warp grid

    const float* w  = d ? whb : whf;
    const float* bh = d ? bhb : bhf;

    // one-time: split this CTA's W slice (48 x 1024) into smem hi/lo
    for (int f = tid; f < 48 * 256; f += 256) {
        int sr = f >> 8;                // 0..47 : gate-col = (sr>>4)*Hz-block, j = sr&15
        int k4 = (f & 255) * 4;
        const float* src = w + (size_t)((sr >> 4) * Hz + jg * 16 + (sr & 15)) * Hz + k4;
        float4 v = *(const float4*)src;
        __nv_bfloat16 h0, l0, h1, l1, h2, l2, h3, l3;
        split_bf16(v.x, h0, l0); split_bf16(v.y, h1, l1);
        split_bf16(v.z, h2, l2); split_bf16(v.w, h3, l3);
        __nv_bfloat16* ph = Whi + sr * LDW + k4;
        __nv_bfloat16* pl = Wlo + sr * LDW + k4;
        ph[0] = h0; ph[1] = h1; ph[2] = h2; ph[3] = h3;
        pl[0] = l0; pl[1] = l1; pl[2] = l2; pl[3] = l3;
    }

    const int jj = tid & 15;
    const int rb = tid >> 4;
    const int jglob = jg * 16 + jj;
    const float b_r = __ldg(&bh[jglob]);
    const float b_z = __ldg(&bh[Hz + jglob]);
    const float b_n = __ldg(&bh[2 * Hz + jglob]);
    __syncthreads();

    // fragment smem byte offsets
    const uint32_t a_off  = (uint32_t)(wm * 16 + (lane & 15)) * (HSTR * 2) + (lane >> 4) * 16;
    const uint32_t w4_off = (uint32_t)(wn * 24 + (lane & 7) + ((lane >> 4) & 1) * 8) * (LDW * 2)
                            + ((lane >> 3) & 1) * 16;
    const uint32_t w2_off = (uint32_t)(wn * 24 + 16 + (lane & 7)) * (LDW * 2)
                            + ((lane >> 3) & 1) * 16;
    // gh fragment -> shg mapping
    const int frow = wm * 16 + (lane >> 2);
    const int fcol0 = wn * 24 + (lane & 3) * 2;

    for (int t = 0; t < Sz; t++) {
        if (t > 0) grid_barrier(phase_base + (unsigned)t);

        size_t prevoff, outoff;
        if (mode == 0) {
            prevoff = ((size_t)d * Sz + (size_t)(t > 0 ? t - 1 : 0)) * Bz * Hz;
            outoff  = ((size_t)d * Sz + t) * Bz * Hz;
        } else {
            int cur = t & 1;
            prevoff = ((size_t)cur * 2 + d) * Bz * Hz;
            outoff  = ((size_t)(cur ^ 1) * 2 + d) * Bz * Hz;
        }
        const __nv_bfloat16* hphi = hhi + prevoff;
        const __nv_bfloat16* hplo = hlo + prevoff;
        const float* gi = gi_base + (size_t)d * gi_dstride + (size_t)t * gi_tstride;

        // prefetch gi and h_prev for pointwise (long-latency, consumed at step end)
        float gir[4], giz[4], gin[4], hpv[4];
#pragma unroll
        for (int i = 0; i < 4; i++) {
            int row = rb + 16 * i;
            size_t gb = (size_t)row * gi_bstride + jglob;
            gir[i] = gi[gb];
            giz[i] = gi[gb + Hz];
            gin[i] = gi[gb + 2 * Hz];
            hpv[i] = (t > 0)
                ? __bfloat162float(hphi[(size_t)row * Hz + jglob])
                  + __bfloat162float(hplo[(size_t)row * Hz + jglob])
                : 0.f;
        }

        if (t > 0) {
            float acc[3][4];
#pragma unroll
            for (int nt = 0; nt < 3; nt++)
#pragma unroll
                for (int e = 0; e < 4; e++) acc[nt][e] = 0.f;

#define HCP(cc, buf) do {                                                     \
            int kt_ = (cc) * 32;                                              \
            uint32_t st_ = hsm + (uint32_t)(buf) * HST_BYTES;                 \
            _Pragma("unroll")                                                 \
            for (int i_ = 0; i_ < 2; i_++) {                                  \
                int L_ = tid * 2 + i_;                                        \
                int op_ = L_ >> 8;                                            \
                int idx_ = L_ & 255;                                          \
                int row_ = idx_ >> 2, seg_ = idx_ & 3;                        \
                const __nv_bfloat16* src_ = (op_ ? hplo : hphi)               \
                    + (size_t)row_ * Hz + kt_ + seg_ * 8;                     \
                uint32_t dst_ = st_ + (uint32_t)op_ * HOP_BYTES               \
                    + (uint32_t)(row_ * (HSTR * 2) + seg_ * 16);              \
                asm volatile("cp.async.cg.shared.global [%0], [%1], 16;"      \
                             :: "r"(dst_), "l"(src_));                        \
            }                                                                 \
            asm volatile("cp.async.commit_group;" ::: "memory");              \
        } while (0)

            HCP(0, 0);
            HCP(1, 1);

            const int NCH = Hz / 32;  // 32 chunks
            for (int c = 0; c < NCH; c++) {
                if (c + 1 < NCH)
                    asm volatile("cp.async.wait_group 1;" ::: "memory");
                else
                    asm volatile("cp.async.wait_group 0;" ::: "memory");
                __syncthreads();

                const uint32_t hb = hsm + (uint32_t)(c & 1) * HST_BYTES;
#pragma unroll
                for (int k16 = 0; k16 < 2; k16++) {
                    const int kg = c * 2 + k16;
                    uint32_t ahi[4], alo[4], wh4[4], wl4[4], wh2[2], wl2[2];
                    ldm_x4(ahi, hb + a_off + k16 * 32);
                    ldm_x4(alo, hb + HOP_BYTES + a_off + k16 * 32);
                    ldm_x4(wh4, whis + w4_off + (uint32_t)kg * 32);
                    ldm_x2(wh2, whis + w2_off + (uint32_t)kg * 32);
                    ldm_x4(wl4, wlos + w4_off + (uint32_t)kg * 32);
                    ldm_x2(wl2, wlos + w2_off + (uint32_t)kg * 32);
                    // pass 1: Ahi * Whi
                    mma_16816(acc[0], ahi, &wh4[0]);
                    mma_16816(acc[1], ahi, &wh4[2]);
                    mma_16816(acc[2], ahi, wh2);
                    // pass 2: Ahi * Wlo
                    mma_16816(acc[0], ahi, &wl4[0]);
                    mma_16816(acc[1], ahi, &wl4[2]);
                    mma_16816(acc[2], ahi, wl2);
                    // pass 3: Alo * Whi
                    mma_16816(acc[0], alo, &wh4[0]);
                    mma_16816(acc[1], alo, &wh4[2]);
                    mma_16816(acc[2], alo, wh2);
                }
                __syncthreads();
                if (c + 2 < NCH) HCP(c + 2, c & 1);
            }
#undef HCP

            // write gh fragments to exchange smem (aliases h stages; MMA done)
#pragma unroll
            for (int nt = 0; nt < 3; nt++) {
                int sc = fcol0 + nt * 8;
                shg[sc * 65 + frow]           = acc[nt][0];
                shg[(sc + 1) * 65 + frow]     = acc[nt][1];
                shg[sc * 65 + frow + 8]       = acc[nt][2];
                shg[(sc + 1) * 65 + frow + 8] = acc[nt][3];
            }
        } else {
            for (int f = tid; f < 48 * 65; f += 256) shg[f] = 0.f;
        }
        __syncthreads();

        // pointwise GRU epilogue
#pragma unroll
        for (int i = 0; i < 4; i++) {
            int row = rb + 16 * i;
            float ghr = shg[jj * 65 + row]        + b_r;
            float ghz = shg[(16 + jj) * 65 + row] + b_z;
            float ghn = shg[(32 + jj) * 65 + row] + b_n;

            float rg = 1.f / (1.f + expf(-(gir[i] + ghr)));
            float zg = 1.f / (1.f + expf(-(giz[i] + ghz)));
            float ng = tanhf(gin[i] + rg * ghn);
            float hnew = (1.f - zg) * ng + zg * hpv[i];

            __nv_bfloat16 hb16, lb16;
            split_bf16(hnew, hb16, lb16);
            size_t oo = outoff + (size_t)row * Hz + jglob;
            hhi[oo] = hb16;
            hlo[oo] = lb16;
            if (mode == 1) {
                dout[((size_t)row * Sz + t) * 2048 + (size_t)d * Hz + jglob] = hnew;
                if (t == Sz - 1)
                    dout[(size_t)Bz * Sz * 2048 + (size_t)row * 2048 + (size_t)d * Hz + jglob] = hnew;
            }
        }
        __syncthreads();
    }
}

// ---------------- host launcher (graph-capturable: 8 kernel nodes) ----------------
extern "C" void kernel_launch(void* const* d_in, const int* in_sizes, int n_in,
                              void* d_out, int out_size)
{
    const float* x      = (const float*)d_in[0];
    const float* w_hh0f = (const float*)d_in[2];
    const float* b_hh0f = (const float*)d_in[4];
    const float* w_hh0b = (const float*)d_in[6];
    const float* b_hh0b = (const float*)d_in[8];
    const float* w_hh1f = (const float*)d_in[10];
    const float* b_ih1f = (const float*)d_in[11];
    const float* b_hh1f = (const float*)d_in[12];
    const float* w_hh1b = (const float*)d_in[14];
    const float* b_ih1b = (const float*)d_in[15];
    const float* b_hh1b = (const float*)d_in[16];
    float* out = (float*)d_out;

    float *gi0, *gi1, *b0;
    __nv_bfloat16 *xhi, *xlo, *W0hi, *W0lo, *W1hi, *W1lo, *h0hi, *h0lo, *h1hi, *h1lo;
    cudaGetSymbolAddress((void**)&gi0,  g_gi0);
    cudaGetSymbolAddress((void**)&gi1,  g_gi1);
    cudaGetSymbolAddress((void**)&b0,   g_b0);
    cudaGetSymbolAddress((void**)&xhi,  g_xhi);
    cudaGetSymbolAddress((void**)&xlo,  g_xlo);
    cudaGetSymbolAddress((void**)&W0hi, g_W0hi);
    cudaGetSymbolAddress((void**)&W0lo, g_W0lo);
    cudaGetSymbolAddress((void**)&W1hi, g_W1hi);
    cudaGetSymbolAddress((void**)&W1lo, g_W1lo);
    cudaGetSymbolAddress((void**)&h0hi, g_h0hi);
    cudaGetSymbolAddress((void**)&h0lo, g_h0lo);
    cudaGetSymbolAddress((void**)&h1hi, g_h1hi);
    cudaGetSymbolAddress((void**)&h1lo, g_h1lo);

    cudaFuncSetAttribute(gru_layer_hmma,
                         cudaFuncAttributeMaxDynamicSharedMemorySize, REC_SMEM);
    cudaFuncSetAttribute(gemm_hmma2,
                         cudaFuncAttributeMaxDynamicSharedMemorySize, GEMM_SMEM_BYTES);

    // 1) prep: split/pack GEMM operands to bf16 hi/lo
    prep_w0_split<<<(G3z * INz + 255) / 256, 256>>>(
        (const float*)d_in[1], (const float*)d_in[5],
        (const float*)d_in[3], (const float*)d_in[7]);
    prep_x_split<<<(Bz * Sz * INz + 255) / 256, 256>>>(x);
    prep_w1_split<<<(G3z * Hz + 255) / 256, 256>>>(
        (const float*)d_in[9], (const float*)d_in[13]);

    // 2) gi0 = x @ [W_ih0f ; rev(W_ih0b)]^T + bias
    gemm_hmma2<<<dim3((2 * G3z) / 128, (Bz * Sz) / 128), 256, GEMM_SMEM_BYTES>>>(
        xhi, xlo, INz, W0hi, W0lo, INz, b0, gi0,
        INz, (size_t)Bz * Sz * G3z, G3z);

    // 3) layer-0 recurrence (HMMA, phases 1..511), writes h0 bf16 hi/lo
    gru_layer_hmma<<<NBLK, 256, REC_SMEM>>>(
        gi0, (size_t)Bz * Sz * G3z, (size_t)G3z, (size_t)Sz * G3z,
        w_hh0f, w_hh0b, b_hh0f, b_hh0b,
        h0hi, h0lo, 0, 0u, nullptr);

    // 4) gi1 = h0_all @ W_ih1^T + bias (per dir)
    for (int dir = 0; dir < 2; dir++) {
        gemm_hmma2<<<dim3(G3z / 128, (Sz * Bz) / 128), 256, GEMM_SMEM_BYTES>>>(
            h0hi + (size_t)dir * Sz * Bz * Hz,
            h0lo + (size_t)dir * Sz * Bz * Hz, Hz,
            W1hi + (size_t)dir * G3z * Hz,
            W1lo + (size_t)dir * G3z * Hz, Hz,
            dir ? b_ih1b : b_ih1f,
            gi1 + (size_t)dir * Sz * Bz * G3z,
            Hz, (size_t)0, G3z);
    }

    // 5) layer-1 recurrence (HMMA, phases 512..1022), writes output
    gru_layer_hmma<<<NBLK, 256, REC_SMEM>>>(
        gi1, (size_t)Sz * Bz * G3z, (size_t)Bz * G3z, (size_t)G3z,
        w_hh1f, w_hh1b, b_hh1f, b_hh1b,
        h1hi, h1lo, 1, (unsigned)(Sz - 1), out);
}

// round 10
// speedup vs baseline: 3.1518x; 1.3206x over previous
#include <cuda_runtime.h>
#include <cuda_bf16.h>
#include <math.h>
#include <stdint.h>

#define Bz  64
#define Sz  512
#define INz 512
#define Hz  1024
#define G3z 3072
#define NBLK 128

// ---------------- scratch (device globals; no allocation allowed) ----------------
__device__ float g_gi0[(size_t)2 * Bz * Sz * G3z];   // [dir][b][s][n]
__device__ float g_gi1[(size_t)2 * Sz * Bz * G3z];   // [dir][s][b][n]
__device__ float g_b0 [2 * G3z];
__device__ unsigned g_count;
__device__ unsigned g_phase;

// pre-split bf16 operands
__device__ __align__(16) __nv_bfloat16 g_xhi [(size_t)Bz * Sz * INz];
__device__ __align__(16) __nv_bfloat16 g_xlo [(size_t)Bz * Sz * INz];
__device__ __align__(16) __nv_bfloat16 g_W0hi[(size_t)2 * G3z * INz];
__device__ __align__(16) __nv_bfloat16 g_W0lo[(size_t)2 * G3z * INz];
__device__ __align__(16) __nv_bfloat16 g_W1hi[(size_t)2 * G3z * Hz];
__device__ __align__(16) __nv_bfloat16 g_W1lo[(size_t)2 * G3z * Hz];
// hidden state, stored ONLY as bf16 hi/lo
__device__ __align__(16) __nv_bfloat16 g_h0hi[(size_t)2 * Sz * Bz * Hz];
__device__ __align__(16) __nv_bfloat16 g_h0lo[(size_t)2 * Sz * Bz * Hz];
__device__ __align__(16) __nv_bfloat16 g_h1hi[(size_t)2 * 2 * Bz * Hz];
__device__ __align__(16) __nv_bfloat16 g_h1lo[(size_t)2 * 2 * Bz * Hz];

__device__ __forceinline__ uint32_t smem_u32(const void* p) {
    uint32_t a;
    asm("{ .reg .u64 t; cvta.to.shared.u64 t, %1; cvt.u32.u64 %0, t; }" : "=r"(a) : "l"(p));
    return a;
}

__device__ __forceinline__ void split_bf16(float v, __nv_bfloat16& hi, __nv_bfloat16& lo) {
    hi = __float2bfloat16(v);
    lo = __float2bfloat16(v - __bfloat162float(hi));
}

// ---------------- grid barrier (release/acquire, monotonic phase) -----------------
__device__ __forceinline__ void grid_barrier(unsigned target)
{
    __syncthreads();
    if (threadIdx.x == 0) {
        unsigned old;
        asm volatile("atom.release.gpu.add.u32 %0, [%1], 1;"
                     : "=r"(old) : "l"(&g_count) : "memory");
        if (old == NBLK - 1) {
            g_count = 0;
            asm volatile("red.release.gpu.add.u32 [%0], 1;"
                         :: "l"(&g_phase) : "memory");
        } else {
            unsigned v;
            do {
                asm volatile("ld.acquire.gpu.u32 %0, [%1];"
                             : "=r"(v) : "l"(&g_phase) : "memory");
            } while (v < target);
        }
    }
    __syncthreads();
}

// ---------------- prep: split/pack operands to bf16 hi/lo -------------------------
__global__ void prep_w0_split(const float* __restrict__ wf, const float* __restrict__ wb,
                              const float* __restrict__ bf, const float* __restrict__ bb)
{
    size_t i = (size_t)blockIdx.x * 256 + threadIdx.x;
    size_t total = (size_t)G3z * INz;
    if (i == 0) { g_count = 0; g_phase = 0; }
    if (i < total) {
        size_t n = i / INz, k = i % INz;
        split_bf16(wf[i], g_W0hi[i], g_W0lo[i]);
        split_bf16(wb[n * INz + (INz - 1 - k)], g_W0hi[total + i], g_W0lo[total + i]);
    }
    if (i < G3z) {
        g_b0[i]       = bf[i];
        g_b0[G3z + i] = bb[i];
    }
}

__global__ void prep_x_split(const float* __restrict__ x)
{
    size_t i = (size_t)blockIdx.x * 256 + threadIdx.x;
    if (i < (size_t)Bz * Sz * INz)
        split_bf16(x[i], g_xhi[i], g_xlo[i]);
}

__global__ void prep_w1_split(const float* __restrict__ wf, const float* __restrict__ wb)
{
    size_t i = (size_t)blockIdx.x * 256 + threadIdx.x;
    size_t total = (size_t)G3z * Hz;
    if (i < total) {
        split_bf16(wf[i], g_W1hi[i], g_W1lo[i]);
        split_bf16(wb[i], g_W1hi[total + i], g_W1lo[total + i]);
    }
}

// ================ shared HMMA primitives (proven R6-R9) ================
__device__ __forceinline__ void ldm_x4(uint32_t* r, uint32_t addr) {
    asm volatile("ldmatrix.sync.aligned.m8n8.x4.shared.b16 {%0,%1,%2,%3}, [%4];"
                 : "=r"(r[0]), "=r"(r[1]), "=r"(r[2]), "=r"(r[3]) : "r"(addr));
}
__device__ __forceinline__ void ldm_x2(uint32_t* r, uint32_t addr) {
    asm volatile("ldmatrix.sync.aligned.m8n8.x2.shared.b16 {%0,%1}, [%2];"
                 : "=r"(r[0]), "=r"(r[1]) : "r"(addr));
}
__device__ __forceinline__ void mma_16816(float* c, const uint32_t* a, const uint32_t* b) {
    asm volatile(
        "mma.sync.aligned.m16n8k16.row.col.f32.bf16.bf16.f32 "
        "{%0,%1,%2,%3}, {%4,%5,%6,%7}, {%8,%9}, {%0,%1,%2,%3};"
        : "+f"(c[0]), "+f"(c[1]), "+f"(c[2]), "+f"(c[3])
        : "r"(a[0]), "r"(a[1]), "r"(a[2]), "r"(a[3]), "r"(b[0]), "r"(b[1]));
}

// ================ HMMA split-bf16 GEMM: C = A @ W^T + bias (unchanged R9) ======
#define LDSTR 40
#define TILE_BYTES (128 * LDSTR * 2)
#define STAGE_BYTES (4 * TILE_BYTES)
#define GEMM_SMEM_BYTES (2 * STAGE_BYTES)

__global__ void __launch_bounds__(256, 2) gemm_hmma2(
    const __nv_bfloat16* __restrict__ Ahi, const __nv_bfloat16* __restrict__ Alo, int lda,
    const __nv_bfloat16* __restrict__ Bhi, const __nv_bfloat16* __restrict__ Blo, int ldw,
    const float* __restrict__ bias,
    float* __restrict__ C,
    int K, size_t dirStride, int N0)
{
    extern __shared__ char sm[];
    const int tid = threadIdx.x, lane = tid & 31, wid = tid >> 5;
    const int wm = wid >> 2, wn = wid & 3;
    const int bn = blockIdx.x, bm = blockIdx.y;

    const __nv_bfloat16* Ahi_b = Ahi + (size_t)bm * 128 * lda;
    const __nv_bfloat16* Alo_b = Alo + (size_t)bm * 128 * lda;
    const __nv_bfloat16* Bhi_b = Bhi + (size_t)bn * 128 * ldw;
    const __nv_bfloat16* Blo_b = Blo + (size_t)bn * 128 * ldw;

    float acc[4][4][4];
#pragma unroll
    for (int mi = 0; mi < 4; mi++)
#pragma unroll
        for (int ni = 0; ni < 4; ni++)
#pragma unroll
            for (int e = 0; e < 4; e++) acc[mi][ni][e] = 0.f;

    const int NC = K / 32;
    const uint32_t smb = smem_u32(sm);

    const uint32_t a_rowoff = (uint32_t)((wm * 64 + (lane & 15)) * LDSTR + (lane >> 4) * 8) * 2;
    const uint32_t b_rowoff = (uint32_t)((wn * 32 + (lane & 7) + ((lane >> 4) & 1) * 8) * LDSTR
                                         + ((lane >> 3) & 1) * 8) * 2;

#define CP_PREFETCH(cc, buf) do {                                             \
        int kt_ = (cc) * 32;                                                  \
        uint32_t stage_ = smb + (uint32_t)(buf) * STAGE_BYTES;                \
        _Pragma("unroll")                                                     \
        for (int i_ = 0; i_ < 8; i_++) {                                      \
            int line_ = tid + 256 * i_;                                       \
            int tile_ = line_ >> 9;                                           \
            int idx_  = line_ & 511;                                          \
            int row_  = idx_ >> 2;                                            \
            int c16_  = idx_ & 3;                                             \
            const __nv_bfloat16* src_;                                        \
            if (tile_ == 0)      src_ = Ahi_b + (size_t)row_ * lda + kt_ + c16_ * 8; \
            else if (tile_ == 1) src_ = Alo_b + (size_t)row_ * lda + kt_ + c16_ * 8; \
            else if (tile_ == 2) src_ = Bhi_b + (size_t)row_ * ldw + kt_ + c16_ * 8; \
            else                 src_ = Blo_b + (size_t)row_ * ldw + kt_ + c16_ * 8; \
            uint32_t dst_ = stage_ + (uint32_t)tile_ * TILE_BYTES             \
                            + (uint32_t)(row_ * (LDSTR * 2) + c16_ * 16);     \
            asm volatile("cp.async.cg.shared.global [%0], [%1], 16;"          \
                         :: "r"(dst_), "l"(src_));                            \
        }                                                                     \
        asm volatile("cp.async.commit_group;" ::: "memory");                  \
    } while (0)

    CP_PREFETCH(0, 0);

    for (int c = 0; c < NC; c++) {
        if (c + 1 < NC) {
            CP_PREFETCH(c + 1, (c + 1) & 1);
            asm volatile("cp.async.wait_group 1;" ::: "memory");
        } else {
            asm volatile("cp.async.wait_group 0;" ::: "memory");
        }
        __syncthreads();

        const uint32_t bufb = smb + (uint32_t)(c & 1) * STAGE_BYTES;
        const uint32_t aoffs[3] = { 0u, 0u, (uint32_t)TILE_BYTES };
        const uint32_t boffs[3] = { 2u * TILE_BYTES, 3u * TILE_BYTES, 2u * TILE_BYTES };
#pragma unroll
        for (int p = 0; p < 3; p++) {
#pragma unroll
            for (int k16 = 0; k16 < 32; k16 += 16) {
                uint32_t af[4][4], bf[2][4];
#pragma unroll
                for (int mi = 0; mi < 4; mi++)
                    ldm_x4(af[mi], bufb + aoffs[p] + a_rowoff
                                   + (uint32_t)(mi * 16 * LDSTR + k16) * 2);
#pragma unroll
                for (int nj = 0; nj < 2; nj++)
                    ldm_x4(bf[nj], bufb + boffs[p] + b_rowoff
                                   + (uint32_t)(nj * 16 * LDSTR + k16) * 2);
#pragma unroll
                for (int mi = 0; mi < 4; mi++)
#pragma unroll
                    for (int ni = 0; ni < 4; ni++)
                        mma_16816(acc[mi][ni], af[mi], &bf[ni >> 1][(ni & 1) * 2]);
            }
        }
        __syncthreads();
    }
#undef CP_PREFETCH

    const int grow = lane >> 2;
    const int gcol = (lane & 3) * 2;
    const int nbase = bn * 128;
    const int dir = nbase / N0;
    const int nn_base = nbase - dir * N0;
    float* Cd = C + (size_t)dir * dirStride;

#pragma unroll
    for (int mi = 0; mi < 4; mi++) {
        size_t m0 = (size_t)bm * 128 + wm * 64 + mi * 16 + grow;
#pragma unroll
        for (int ni = 0; ni < 4; ni++) {
            int nloc = wn * 32 + ni * 8 + gcol;
            float bx = __ldg(&bias[nbase + nloc]);
            float by = __ldg(&bias[nbase + nloc + 1]);
            float2 v0 = make_float2(acc[mi][ni][0] + bx, acc[mi][ni][1] + by);
            float2 v1 = make_float2(acc[mi][ni][2] + bx, acc[mi][ni][3] + by);
            *(float2*)(Cd + m0 * G3z + nn_base + nloc)       = v0;
            *(float2*)(Cd + (m0 + 8) * G3z + nn_base + nloc) = v1;
        }
    }
}

// ================ persistent HMMA recurrent layer (512 threads, k-split) ==========
// 128 CTAs: d = bx>>6, jg = bx&63 (16 H-cols -> 48 gate-cols).
// 16 warps: wk = wid>>3 splits the K dim (k16 0/1 of each 32-K chunk);
//           wq = wid&7: wm = wq&3 (16 M rows), wn = wq>>2 (24 gate cols).
// h tiles: 3-stage cp.async pipeline, 128B swizzled rows [hi(32bf16)|lo(32bf16)].
// Partial accs of the two k-groups summed through the smem exchange buffer.
#define LDW  1032                       // bf16 stride for W slice rows
#define WT_BYTES (48 * LDW * 2)         // 99072 per hi/lo
#define HSTAGE 8192                     // 64 rows x 128B swizzled
#define NSTG 3
#define REC_SMEM (2 * WT_BYTES + NSTG * HSTAGE)   // 222720
#define RTHREADS 512

__global__ void __launch_bounds__(RTHREADS) gru_layer_hmma(
    const float* __restrict__ gi_base, size_t gi_dstride, size_t gi_tstride, size_t gi_bstride,
    const float* __restrict__ whf, const float* __restrict__ whb,
    const float* __restrict__ bhf, const float* __restrict__ bhb,
    __nv_bfloat16* __restrict__ hhi, __nv_bfloat16* __restrict__ hlo,
    int mode, unsigned phase_base, float* __restrict__ dout)
{
    extern __shared__ char sm[];
    __nv_bfloat16* Whi = (__nv_bfloat16*)sm;
    __nv_bfloat16* Wlo = (__nv_bfloat16*)(sm + WT_BYTES);
    float* shg = (float*)(sm + 2 * WT_BYTES);        // aliases h stages (post-MMA)
    const uint32_t whis = smem_u32(Whi);
    const uint32_t wlos = smem_u32(Wlo);
    const uint32_t hsm  = smem_u32(sm + 2 * WT_BYTES);

    const int d  = blockIdx.x >> 6;
    const int jg = blockIdx.x & 63;
    const int tid = threadIdx.x, lane = tid & 31, wid = tid >> 5;
    const int wk = wid >> 3;                 // k16 group within chunk
    const int wq = wid & 7;
    const int wm = wq & 3, wn = wq >> 2;     // 4m x 2n

    const float* w  = d ? whb : whf;
    const float* bh = d ? bhb : bhf;

    // one-time: split this CTA's W slice (48 x 1024) into smem hi/lo
    for (int f = tid; f < 48 * 256; f += RTHREADS) {
        int sr = f >> 8;
        int k4 = (f & 255) * 4;
        const float* src = w + (size_t)((sr >> 4) * Hz + jg * 16 + (sr & 15)) * Hz + k4;
        float4 v = *(const float4*)src;
        __nv_bfloat16 h0, l0, h1, l1, h2, l2, h3, l3;
        split_bf16(v.x, h0, l0); split_bf16(v.y, h1, l1);
        split_bf16(v.z, h2, l2); split_bf16(v.w, h3, l3);
        __nv_bfloat16* ph = Whi + sr * LDW + k4;
        __nv_bfloat16* pl = Wlo + sr * LDW + k4;
        ph[0] = h0; ph[1] = h1; ph[2] = h2; ph[3] = h3;
        pl[0] = l0; pl[1] = l1; pl[2] = l2; pl[3] = l3;
    }

    const int jj = tid & 15;
    const int rb = tid >> 4;                 // 0..31, 2 batch rows per thread
    const int jglob = jg * 16 + jj;
    const float b_r = __ldg(&bh[jglob]);
    const float b_z = __ldg(&bh[Hz + jglob]);
    const float b_n = __ldg(&bh[2 * Hz + jglob]);
    __syncthreads();

    // W fragment smem byte offsets (kg selects +kg*32)
    const uint32_t w4_off = (uint32_t)(wn * 24 + (lane & 7) + ((lane >> 4) & 1) * 8) * (LDW * 2)
                            + ((lane >> 3) & 1) * 16;
    const uint32_t w2_off = (uint32_t)(wn * 24 + 16 + (lane & 7)) * (LDW * 2)
                            + ((lane >> 3) & 1) * 16;
    // h fragment addresses (swizzled 128B rows; fixed per thread, + stage base)
    const int arow  = wm * 16 + (lane & 15);
    const int ahalf = lane >> 4;
    const uint32_t aoff_hi = (uint32_t)(arow * 128 + (((wk * 2 + ahalf)     ^ (arow & 7)) * 16));
    const uint32_t aoff_lo = (uint32_t)(arow * 128 + (((4 + wk * 2 + ahalf) ^ (arow & 7)) * 16));
    // cp.async per-thread mapping
    const int prow = tid >> 3;
    const int pseg = tid & 7;
    const uint32_t pdst_off = (uint32_t)(prow * 128 + ((pseg ^ (prow & 7)) * 16));
    // gh fragment -> shg mapping
    const int frow = wm * 16 + (lane >> 2);
    const int fcol0 = wn * 24 + (lane & 3) * 2;

    for (int t = 0; t < Sz; t++) {
        if (t > 0) grid_barrier(phase_base + (unsigned)t);

        size_t prevoff, outoff;
        if (mode == 0) {
            prevoff = ((size_t)d * Sz + (size_t)(t > 0 ? t - 1 : 0)) * Bz * Hz;
            outoff  = ((size_t)d * Sz + t) * Bz * Hz;
        } else {
            int cur = t & 1;
            prevoff = ((size_t)cur * 2 + d) * Bz * Hz;
            outoff  = ((size_t)(cur ^ 1) * 2 + d) * Bz * Hz;
        }
        const __nv_bfloat16* hphi = hhi + prevoff;
        const __nv_bfloat16* hplo = hlo + prevoff;
        const float* gi = gi_base + (size_t)d * gi_dstride + (size_t)t * gi_tstride;

        // prefetch gi and h_prev for pointwise (2 rows per thread)
        float gir[2], giz[2], gin[2], hpv[2];
#pragma unroll
        for (int i = 0; i < 2; i++) {
            int row = rb + 32 * i;
            size_t gb = (size_t)row * gi_bstride + jglob;
            gir[i] = gi[gb];
            giz[i] = gi[gb + Hz];
            gin[i] = gi[gb + 2 * Hz];
            hpv[i] = (t > 0)
                ? __bfloat162float(hphi[(size_t)row * Hz + jglob])
                  + __bfloat162float(hplo[(size_t)row * Hz + jglob])
                : 0.f;
        }

        if (t > 0) {
            float acc[3][4];
#pragma unroll
            for (int nt = 0; nt < 3; nt++)
#pragma unroll
                for (int e = 0; e < 4; e++) acc[nt][e] = 0.f;

#define HCP(cc, stg) do {                                                     \
            int kt_ = (cc) * 32;                                              \
            const __nv_bfloat16* src_ = (pseg < 4 ? hphi : hplo)              \
                + (size_t)prow * Hz + kt_ + (pseg & 3) * 8;                   \
            uint32_t dst_ = hsm + (uint32_t)(stg) * HSTAGE + pdst_off;        \
            asm volatile("cp.async.cg.shared.global [%0], [%1], 16;"          \
                         :: "r"(dst_), "l"(src_));                            \
            asm volatile("cp.async.commit_group;" ::: "memory");              \
        } while (0)

            HCP(0, 0);
            HCP(1, 1);

            const int NCH = Hz / 32;  // 32 chunks
            for (int c = 0; c < NCH; c++) {
                if (c + 1 < NCH)
                    asm volatile("cp.async.wait_group 1;" ::: "memory");
                else
                    asm volatile("cp.async.wait_group 0;" ::: "memory");
                __syncthreads();
                if (c + 2 < NCH) HCP(c + 2, (c + 2) % NSTG);

                const uint32_t hb = hsm + (uint32_t)(c % NSTG) * HSTAGE;
                const int kg = c * 2 + wk;
                uint32_t ahi[4], alo[4], wh4[4], wl4[4], wh2[2], wl2[2];
                ldm_x4(ahi, hb + aoff_hi);
                ldm_x4(alo, hb + aoff_lo);
                ldm_x4(wh4, whis + w4_off + (uint32_t)kg * 32);
                ldm_x2(wh2, whis + w2_off + (uint32_t)kg * 32);
                ldm_x4(wl4, wlos + w4_off + (uint32_t)kg * 32);
                ldm_x2(wl2, wlos + w2_off + (uint32_t)kg * 32);
                // pass 1: Ahi * Whi
                mma_16816(acc[0], ahi, &wh4[0]);
                mma_16816(acc[1], ahi, &wh4[2]);
                mma_16816(acc[2], ahi, wh2);
                // pass 2: Ahi * Wlo
                mma_16816(acc[0], ahi, &wl4[0]);
                mma_16816(acc[1], ahi, &wl4[2]);
                mma_16816(acc[2], ahi, wl2);
                // pass 3: Alo * Whi
                mma_16816(acc[0], alo, &wh4[0]);
                mma_16816(acc[1], alo, &wh4[2]);
                mma_16816(acc[2], alo, wh2);
            }
#undef HCP
            __syncthreads();   // all MMA done before shg overwrites stage smem

            // combine k-halves through the exchange buffer
            if (wk == 0) {
#pragma unroll
                for (int nt = 0; nt < 3; nt++) {
                    int sc = fcol0 + nt * 8;
                    shg[sc * 65 + frow]           = acc[nt][0];
                    shg[(sc + 1) * 65 + frow]     = acc[nt][1];
                    shg[sc * 65 + frow + 8]       = acc[nt][2];
                    shg[(sc + 1) * 65 + frow + 8] = acc[nt][3];
                }
            }
            __syncthreads();
            if (wk == 1) {
#pragma unroll
                for (int nt = 0; nt < 3; nt++) {
                    int sc = fcol0 + nt * 8;
                    shg[sc * 65 + frow]           += acc[nt][0];
                    shg[(sc + 1) * 65 + frow]     += acc[nt][1];
                    shg[sc * 65 + frow + 8]       += acc[nt][2];
                    shg[(sc + 1) * 65 + frow + 8] += acc[nt][3];
                }
            }
        } else {
            for (int f = tid; f < 48 * 65; f += RTHREADS) shg[f] = 0.f;
        }
        __syncthreads();

        // pointwise GRU epilogue (2 rows per thread)
#pragma unroll
        for (int i = 0; i < 2; i++) {
            int row = rb + 32 * i;
            float ghr = shg[jj * 65 + row]        + b_r;
            float ghz = shg[(16 + jj) * 65 + row] + b_z;
            float ghn = shg[(32 + jj) * 65 + row] + b_n;

            float rg = 1.f / (1.f + expf(-(gir[i] + ghr)));
            float zg = 1.f / (1.f + expf(-(giz[i] + ghz)));
            float ng = tanhf(gin[i] + rg * ghn);
            float hnew = (1.f - zg) * ng + zg * hpv[i];

            __nv_bfloat16 hb16, lb16;
            split_bf16(hnew, hb16, lb16);
            size_t oo = outoff + (size_t)row * Hz + jglob;
            hhi[oo] = hb16;
            hlo[oo] = lb16;
            if (mode == 1) {
                dout[((size_t)row * Sz + t) * 2048 + (size_t)d * Hz + jglob] = hnew;
                if (t == Sz - 1)
                    dout[(size_t)Bz * Sz * 2048 + (size_t)row * 2048 + (size_t)d * Hz + jglob] = hnew;
            }
        }
        __syncthreads();
    }
}

// ---------------- host launcher (graph-capturable: 8 kernel nodes) ----------------
extern "C" void kernel_launch(void* const* d_in, const int* in_sizes, int n_in,
                              void* d_out, int out_size)
{
    const float* x      = (const float*)d_in[0];
    const float* w_hh0f = (const float*)d_in[2];
    const float* b_hh0f = (const float*)d_in[4];
    const float* w_hh0b = (const float*)d_in[6];
    const float* b_hh0b = (const float*)d_in[8];
    const float* w_hh1f = (const float*)d_in[10];
    const float* b_ih1f = (const float*)d_in[11];
    const float* b_hh1f = (const float*)d_in[12];
    const float* w_hh1b = (const float*)d_in[14];
    const float* b_ih1b = (const float*)d_in[15];
    const float* b_hh1b = (const float*)d_in[16];
    float* out = (float*)d_out;

    float *gi0, *gi1, *b0;
    __nv_bfloat16 *xhi, *xlo, *W0hi, *W0lo, *W1hi, *W1lo, *h0hi, *h0lo, *h1hi, *h1lo;
    cudaGetSymbolAddress((void**)&gi0,  g_gi0);
    cudaGetSymbolAddress((void**)&gi1,  g_gi1);
    cudaGetSymbolAddress((void**)&b0,   g_b0);
    cudaGetSymbolAddress((void**)&xhi,  g_xhi);
    cudaGetSymbolAddress((void**)&xlo,  g_xlo);
    cudaGetSymbolAddress((void**)&W0hi, g_W0hi);
    cudaGetSymbolAddress((void**)&W0lo, g_W0lo);
    cudaGetSymbolAddress((void**)&W1hi, g_W1hi);
    cudaGetSymbolAddress((void**)&W1lo, g_W1lo);
    cudaGetSymbolAddress((void**)&h0hi, g_h0hi);
    cudaGetSymbolAddress((void**)&h0lo, g_h0lo);
    cudaGetSymbolAddress((void**)&h1hi, g_h1hi);
    cudaGetSymbolAddress((void**)&h1lo, g_h1lo);

    cudaFuncSetAttribute(gru_layer_hmma,
                         cudaFuncAttributeMaxDynamicSharedMemorySize, REC_SMEM);
    cudaFuncSetAttribute(gemm_hmma2,
                         cudaFuncAttributeMaxDynamicSharedMemorySize, GEMM_SMEM_BYTES);

    // 1) prep: split/pack GEMM operands to bf16 hi/lo
    prep_w0_split<<<(G3z * INz + 255) / 256, 256>>>(
        (const float*)d_in[1], (const float*)d_in[5],
        (const float*)d_in[3], (const float*)d_in[7]);
    prep_x_split<<<(Bz * Sz * INz + 255) / 256, 256>>>(x);
    prep_w1_split<<<(G3z * Hz + 255) / 256, 256>>>(
        (const float*)d_in[9], (const float*)d_in[13]);

    // 2) gi0 = x @ [W_ih0f ; rev(W_ih0b)]^T + bias
    gemm_hmma2<<<dim3((2 * G3z) / 128, (Bz * Sz) / 128), 256, GEMM_SMEM_BYTES>>>(
        xhi, xlo, INz, W0hi, W0lo, INz, b0, gi0,
        INz, (size_t)Bz * Sz * G3z, G3z);

    // 3) layer-0 recurrence (HMMA, phases 1..511), writes h0 bf16 hi/lo
    gru_layer_hmma<<<NBLK, RTHREADS, REC_SMEM>>>(
        gi0, (size_t)Bz * Sz * G3z, (size_t)G3z, (size_t)Sz * G3z,
        w_hh0f, w_hh0b, b_hh0f, b_hh0b,
        h0hi, h0lo, 0, 0u, nullptr);

    // 4) gi1 = h0_all @ W_ih1^T + bias (per dir)
    for (int dir = 0; dir < 2; dir++) {
        gemm_hmma2<<<dim3(G3z / 128, (Sz * Bz) / 128), 256, GEMM_SMEM_BYTES>>>(
            h0hi + (size_t)dir * Sz * Bz * Hz,
            h0lo + (size_t)dir * Sz * Bz * Hz, Hz,
            W1hi + (size_t)dir * G3z * Hz,
            W1lo + (size_t)dir * G3z * Hz, Hz,
            dir ? b_ih1b : b_ih1f,
            gi1 + (size_t)dir * Sz * Bz * G3z,
            Hz, (size_t)0, G3z);
    }

    // 5) layer-1 recurrence (HMMA, phases 512..1022), writes output
    gru_layer_hmma<<<NBLK, RTHREADS, REC_SMEM>>>(
        gi1, (size_t)Sz * Bz * G3z, (size_t)Bz * G3z, (size_t)G3z,
        w_hh1f, w_hh1b, b_hh1f, b_hh1b,
        h1hi, h1lo, 1, (unsigned)(Sz - 1), out);
}

// round 11
// speedup vs baseline: 3.4028x; 1.0796x over previous
#include <cuda_runtime.h>
#include <cuda_bf16.h>
#include <math.h>
#include <stdint.h>

#define Bz  64
#define Sz  512
#define INz 512
#define Hz  1024
#define G3z 3072
#define NBLK 128

// ---------------- scratch (device globals; no allocation allowed) ----------------
__device__ float g_gi0[(size_t)2 * Bz * Sz * G3z];   // [dir][b][s][n]
__device__ float g_gi1[(size_t)2 * Sz * Bz * G3z];   // [dir][s][b][n]
__device__ float g_b0 [2 * G3z];
__device__ unsigned g_count;
__device__ unsigned g_phase;

// pre-split bf16 operands
__device__ __align__(16) __nv_bfloat16 g_xhi [(size_t)Bz * Sz * INz];
__device__ __align__(16) __nv_bfloat16 g_xlo [(size_t)Bz * Sz * INz];
__device__ __align__(16) __nv_bfloat16 g_W0hi[(size_t)2 * G3z * INz];
__device__ __align__(16) __nv_bfloat16 g_W0lo[(size_t)2 * G3z * INz];
__device__ __align__(16) __nv_bfloat16 g_W1hi[(size_t)2 * G3z * Hz];
__device__ __align__(16) __nv_bfloat16 g_W1lo[(size_t)2 * G3z * Hz];
// hidden state, stored ONLY as bf16 hi/lo
__device__ __align__(16) __nv_bfloat16 g_h0hi[(size_t)2 * Sz * Bz * Hz];
__device__ __align__(16) __nv_bfloat16 g_h0lo[(size_t)2 * Sz * Bz * Hz];
__device__ __align__(16) __nv_bfloat16 g_h1hi[(size_t)2 * 2 * Bz * Hz];
__device__ __align__(16) __nv_bfloat16 g_h1lo[(size_t)2 * 2 * Bz * Hz];

__device__ __forceinline__ uint32_t smem_u32(const void* p) {
    uint32_t a;
    asm("{ .reg .u64 t; cvta.to.shared.u64 t, %1; cvt.u32.u64 %0, t; }" : "=r"(a) : "l"(p));
    return a;
}

__device__ __forceinline__ void split_bf16(float v, __nv_bfloat16& hi, __nv_bfloat16& lo) {
    hi = __float2bfloat16(v);
    lo = __float2bfloat16(v - __bfloat162float(hi));
}

// ---------------- grid barrier (release/acquire, monotonic phase) -----------------
__device__ __forceinline__ void grid_barrier(unsigned target)
{
    __syncthreads();
    if (threadIdx.x == 0) {
        unsigned old;
        asm volatile("atom.release.gpu.add.u32 %0, [%1], 1;"
                     : "=r"(old) : "l"(&g_count) : "memory");
        if (old == NBLK - 1) {
            g_count = 0;
            asm volatile("red.release.gpu.add.u32 [%0], 1;"
                         :: "l"(&g_phase) : "memory");
        } else {
            unsigned v;
            do {
                asm volatile("ld.acquire.gpu.u32 %0, [%1];"
                             : "=r"(v) : "l"(&g_phase) : "memory");
            } while (v < target);
        }
    }
    __syncthreads();
}

// ---------------- prep: split/pack operands to bf16 hi/lo -------------------------
__global__ void prep_w0_split(const float* __restrict__ wf, const float* __restrict__ wb,
                              const float* __restrict__ bf, const float* __restrict__ bb)
{
    size_t i = (size_t)blockIdx.x * 256 + threadIdx.x;
    size_t total = (size_t)G3z * INz;
    if (i == 0) { g_count = 0; g_phase = 0; }
    if (i < total) {
        size_t n = i / INz, k = i % INz;
        split_bf16(wf[i], g_W0hi[i], g_W0lo[i]);
        split_bf16(wb[n * INz + (INz - 1 - k)], g_W0hi[total + i], g_W0lo[total + i]);
    }
    if (i < G3z) {
        g_b0[i]       = bf[i];
        g_b0[G3z + i] = bb[i];
    }
}

__global__ void prep_x_split(const float* __restrict__ x)
{
    size_t i = (size_t)blockIdx.x * 256 + threadIdx.x;
    if (i < (size_t)Bz * Sz * INz)
        split_bf16(x[i], g_xhi[i], g_xlo[i]);
}

__global__ void prep_w1_split(const float* __restrict__ wf, const float* __restrict__ wb)
{
    size_t i = (size_t)blockIdx.x * 256 + threadIdx.x;
    size_t total = (size_t)G3z * Hz;
    if (i < total) {
        split_bf16(wf[i], g_W1hi[i], g_W1lo[i]);
        split_bf16(wb[i], g_W1hi[total + i], g_W1lo[total + i]);
    }
}

// ================ shared HMMA primitives (proven R6-R10) ================
__device__ __forceinline__ void ldm_x4(uint32_t* r, uint32_t addr) {
    asm volatile("ldmatrix.sync.aligned.m8n8.x4.shared.b16 {%0,%1,%2,%3}, [%4];"
                 : "=r"(r[0]), "=r"(r[1]), "=r"(r[2]), "=r"(r[3]) : "r"(addr));
}
__device__ __forceinline__ void ldm_x2(uint32_t* r, uint32_t addr) {
    asm volatile("ldmatrix.sync.aligned.m8n8.x2.shared.b16 {%0,%1}, [%2];"
                 : "=r"(r[0]), "=r"(r[1]) : "r"(addr));
}
__device__ __forceinline__ void mma_16816(float* c, const uint32_t* a, const uint32_t* b) {
    asm volatile(
        "mma.sync.aligned.m16n8k16.row.col.f32.bf16.bf16.f32 "
        "{%0,%1,%2,%3}, {%4,%5,%6,%7}, {%8,%9}, {%0,%1,%2,%3};"
        : "+f"(c[0]), "+f"(c[1]), "+f"(c[2]), "+f"(c[3])
        : "r"(a[0]), "r"(a[1]), "r"(a[2]), "r"(a[3]), "r"(b[0]), "r"(b[1]));
}

// ================ HMMA split-bf16 GEMM v3: C = A @ W^T + bias ================
// Swizzled unpadded tiles (128 rows x 64B), 3-stage cp.async, one sync/chunk,
// register-reuse pass order (24 ldsm/chunk vs 36). 8 warps = 2(m) x 4(n).
#define GT_BYTES 8192                       // one operand tile: 128 x 32 bf16
#define GS_BYTES (4 * GT_BYTES)             // Ahi, Alo, Bhi, Blo = 32768
#define GNSTG 3
#define GEMM_SMEM_BYTES (GNSTG * GS_BYTES)  // 98304 -> 2 CTAs/SM

__global__ void __launch_bounds__(256, 2) gemm_hmma3(
    const __nv_bfloat16* __restrict__ Ahi, const __nv_bfloat16* __restrict__ Alo, int lda,
    const __nv_bfloat16* __restrict__ Bhi, const __nv_bfloat16* __restrict__ Blo, int ldw,
    const float* __restrict__ bias,
    float* __restrict__ C,
    int K, size_t dirStride, int N0)
{
    extern __shared__ char sm[];
    const int tid = threadIdx.x, lane = tid & 31, wid = tid >> 5;
    const int wm = wid >> 2, wn = wid & 3;
    const int bn = blockIdx.x, bm = blockIdx.y;

    const __nv_bfloat16* Ahi_b = Ahi + (size_t)bm * 128 * lda;
    const __nv_bfloat16* Alo_b = Alo + (size_t)bm * 128 * lda;
    const __nv_bfloat16* Bhi_b = Bhi + (size_t)bn * 128 * ldw;
    const __nv_bfloat16* Blo_b = Blo + (size_t)bn * 128 * ldw;

    float acc[4][4][4];
#pragma unroll
    for (int mi = 0; mi < 4; mi++)
#pragma unroll
        for (int ni = 0; ni < 4; ni++)
#pragma unroll
            for (int e = 0; e < 4; e++) acc[mi][ni][e] = 0.f;

    const int NC = K / 32;
    const uint32_t smb = smem_u32(sm);

    // per-thread fragment address precomputation (swizzled 64B rows)
    const int half_a = lane >> 4;            // A k-half
    const int half_b = (lane >> 3) & 1;      // B k-half
    uint32_t a_b64[4], b_b64[2];
    int a_q[4], b_q[2];
#pragma unroll
    for (int mi = 0; mi < 4; mi++) {
        int row = wm * 64 + (lane & 15) + mi * 16;
        a_b64[mi] = (uint32_t)row * 64;
        a_q[mi] = (row >> 1) & 3;
    }
#pragma unroll
    for (int nj = 0; nj < 2; nj++) {
        int row = wn * 32 + (lane & 7) + ((lane >> 4) & 1) * 8 + nj * 16;
        b_b64[nj] = (uint32_t)row * 64;
        b_q[nj] = (row >> 1) & 3;
    }
    // producer line mapping (8 lines of 16B per thread per stage)
    const int prow = (tid & 511) >> 2;       // reused per i below

#define CP_PREFETCH(cc, stg) do {                                             \
        int kt_ = (cc) * 32;                                                  \
        uint32_t base_ = smb + (uint32_t)(stg) * GS_BYTES;                    \
        _Pragma("unroll")                                                     \
        for (int i_ = 0; i_ < 8; i_++) {                                      \
            int line_ = tid + 256 * i_;                                       \
            int tile_ = line_ >> 9;                                           \
            int idx_  = line_ & 511;                                          \
            int row_  = idx_ >> 2;                                            \
            int seg_  = idx_ & 3;                                             \
            const __nv_bfloat16* src_;                                        \
            if (tile_ == 0)      src_ = Ahi_b + (size_t)row_ * lda + kt_ + seg_ * 8; \
            else if (tile_ == 1) src_ = Alo_b + (size_t)row_ * lda + kt_ + seg_ * 8; \
            else if (tile_ == 2) src_ = Bhi_b + (size_t)row_ * ldw + kt_ + seg_ * 8; \
            else                 src_ = Blo_b + (size_t)row_ * ldw + kt_ + seg_ * 8; \
            uint32_t dst_ = base_ + (uint32_t)tile_ * GT_BYTES                \
                            + (uint32_t)row_ * 64                             \
                            + (uint32_t)(((seg_ ^ ((row_ >> 1) & 3))) << 4);  \
            asm volatile("cp.async.cg.shared.global [%0], [%1], 16;"          \
                         :: "r"(dst_), "l"(src_));                            \
        }                                                                     \
        asm volatile("cp.async.commit_group;" ::: "memory");                  \
    } while (0)

    CP_PREFETCH(0, 0);
    CP_PREFETCH(1, 1);

    for (int c = 0; c < NC; c++) {
        if (c + 1 < NC)
            asm volatile("cp.async.wait_group 1;" ::: "memory");
        else
            asm volatile("cp.async.wait_group 0;" ::: "memory");
        __syncthreads();
        if (c + 2 < NC) CP_PREFETCH(c + 2, (c + 2) % GNSTG);

        const uint32_t st = smb + (uint32_t)(c % GNSTG) * GS_BYTES;
#pragma unroll
        for (int kh = 0; kh < 2; kh++) {
            uint32_t afr[4][4], bhi[2][4], blo[2][4];
            const uint32_t sa = (uint32_t)(2 * kh + half_a);
            const uint32_t sb = (uint32_t)(2 * kh + half_b);
#pragma unroll
            for (int mi = 0; mi < 4; mi++)
                ldm_x4(afr[mi], st + a_b64[mi] + (((sa ^ a_q[mi])) << 4));
#pragma unroll
            for (int nj = 0; nj < 2; nj++) {
                ldm_x4(bhi[nj], st + 2u * GT_BYTES + b_b64[nj] + ((sb ^ b_q[nj]) << 4));
                ldm_x4(blo[nj], st + 3u * GT_BYTES + b_b64[nj] + ((sb ^ b_q[nj]) << 4));
            }
            // pass 1: Ahi * Bhi ; pass 2: Ahi * Blo
#pragma unroll
            for (int mi = 0; mi < 4; mi++)
#pragma unroll
                for (int ni = 0; ni < 4; ni++) {
                    mma_16816(acc[mi][ni], afr[mi], &bhi[ni >> 1][(ni & 1) * 2]);
                    mma_16816(acc[mi][ni], afr[mi], &blo[ni >> 1][(ni & 1) * 2]);
                }
            // pass 3: Alo * Bhi (reuse A fragment registers)
#pragma unroll
            for (int mi = 0; mi < 4; mi++)
                ldm_x4(afr[mi], st + GT_BYTES + a_b64[mi] + ((sa ^ a_q[mi]) << 4));
#pragma unroll
            for (int mi = 0; mi < 4; mi++)
#pragma unroll
                for (int ni = 0; ni < 4; ni++)
                    mma_16816(acc[mi][ni], afr[mi], &bhi[ni >> 1][(ni & 1) * 2]);
        }
    }
#undef CP_PREFETCH

    // epilogue: add bias, scatter to packed-dir layout
    const int grow = lane >> 2;
    const int gcol = (lane & 3) * 2;
    const int nbase = bn * 128;
    const int dir = nbase / N0;
    const int nn_base = nbase - dir * N0;
    float* Cd = C + (size_t)dir * dirStride;
    (void)prow;

#pragma unroll
    for (int mi = 0; mi < 4; mi++) {
        size_t m0 = (size_t)bm * 128 + wm * 64 + mi * 16 + grow;
#pragma unroll
        for (int ni = 0; ni < 4; ni++) {
            int nloc = wn * 32 + ni * 8 + gcol;
            float bx = __ldg(&bias[nbase + nloc]);
            float by = __ldg(&bias[nbase + nloc + 1]);
            float2 v0 = make_float2(acc[mi][ni][0] + bx, acc[mi][ni][1] + by);
            float2 v1 = make_float2(acc[mi][ni][2] + bx, acc[mi][ni][3] + by);
            *(float2*)(Cd + m0 * G3z + nn_base + nloc)       = v0;
            *(float2*)(Cd + (m0 + 8) * G3z + nn_base + nloc) = v1;
        }
    }
}

// ================ persistent HMMA recurrent layer (unchanged R10) ==========
#define LDW  1032
#define WT_BYTES (48 * LDW * 2)
#define HSTAGE 8192
#define NSTG 3
#define REC_SMEM (2 * WT_BYTES + NSTG * HSTAGE)
#define RTHREADS 512

__global__ void __launch_bounds__(RTHREADS) gru_layer_hmma(
    const float* __restrict__ gi_base, size_t gi_dstride, size_t gi_tstride, size_t gi_bstride,
    const float* __restrict__ whf, const float* __restrict__ whb,
    const float* __restrict__ bhf, const float* __restrict__ bhb,
    __nv_bfloat16* __restrict__ hhi, __nv_bfloat16* __restrict__ hlo,
    int mode, unsigned phase_base, float* __restrict__ dout)
{
    extern __shared__ char sm[];
    __nv_bfloat16* Whi = (__nv_bfloat16*)sm;
    __nv_bfloat16* Wlo = (__nv_bfloat16*)(sm + WT_BYTES);
    float* shg = (float*)(sm + 2 * WT_BYTES);
    const uint32_t whis = smem_u32(Whi);
    const uint32_t wlos = smem_u32(Wlo);
    const uint32_t hsm  = smem_u32(sm + 2 * WT_BYTES);

    const int d  = blockIdx.x >> 6;
    const int jg = blockIdx.x & 63;
    const int tid = threadIdx.x, lane = tid & 31, wid = tid >> 5;
    const int wk = wid >> 3;
    const int wq = wid & 7;
    const int wm = wq & 3, wn = wq >> 2;

    const float* w  = d ? whb : whf;
    const float* bh = d ? bhb : bhf;

    for (int f = tid; f < 48 * 256; f += RTHREADS) {
        int sr = f >> 8;
        int k4 = (f & 255) * 4;
        const float* src = w + (size_t)((sr >> 4) * Hz + jg * 16 + (sr & 15)) * Hz + k4;
        float4 v = *(const float4*)src;
        __nv_bfloat16 h0, l0, h1, l1, h2, l2, h3, l3;
        split_bf16(v.x, h0, l0); split_bf16(v.y, h1, l1);
        split_bf16(v.z, h2, l2); split_bf16(v.w, h3, l3);
        __nv_bfloat16* ph = Whi + sr * LDW + k4;
        __nv_bfloat16* pl = Wlo + sr * LDW + k4;
        ph[0] = h0; ph[1] = h1; ph[2] = h2; ph[3] = h3;
        pl[0] = l0; pl[1] = l1; pl[2] = l2; pl[3] = l3;
    }

    const int jj = tid & 15;
    const int rb = tid >> 4;
    const int jglob = jg * 16 + jj;
    const float b_r = __ldg(&bh[jglob]);
    const float b_z = __ldg(&bh[Hz + jglob]);
    const float b_n = __ldg(&bh[2 * Hz + jglob]);
    __syncthreads();

    const uint32_t w4_off = (uint32_t)(wn * 24 + (lane & 7) + ((lane >> 4) & 1) * 8) * (LDW * 2)
                            + ((lane >> 3) & 1) * 16;
    const uint32_t w2_off = (uint32_t)(wn * 24 + 16 + (lane & 7)) * (LDW * 2)
                            + ((lane >> 3) & 1) * 16;
    const int arow  = wm * 16 + (lane & 15);
    const int ahalf = lane >> 4;
    const uint32_t aoff_hi = (uint32_t)(arow * 128 + (((wk * 2 + ahalf)     ^ (arow & 7)) * 16));
    const uint32_t aoff_lo = (uint32_t)(arow * 128 + (((4 + wk * 2 + ahalf) ^ (arow & 7)) * 16));
    const int prow = tid >> 3;
    const int pseg = tid & 7;
    const uint32_t pdst_off = (uint32_t)(prow * 128 + ((pseg ^ (prow & 7)) * 16));
    const int frow = wm * 16 + (lane >> 2);
    const int fcol0 = wn * 24 + (lane & 3) * 2;

    for (int t = 0; t < Sz; t++) {
        if (t > 0) grid_barrier(phase_base + (unsigned)t);

        size_t prevoff, outoff;
        if (mode == 0) {
            prevoff = ((size_t)d * Sz + (size_t)(t > 0 ? t - 1 : 0)) * Bz * Hz;
            outoff  = ((size_t)d * Sz + t) * Bz * Hz;
        } else {
            int cur = t & 1;
            prevoff = ((size_t)cur * 2 + d) * Bz * Hz;
            outoff  = ((size_t)(cur ^ 1) * 2 + d) * Bz * Hz;
        }
        const __nv_bfloat16* hphi = hhi + prevoff;
        const __nv_bfloat16* hplo = hlo + prevoff;
        const float* gi = gi_base + (size_t)d * gi_dstride + (size_t)t * gi_tstride;

        float gir[2], giz[2], gin[2], hpv[2];
#pragma unroll
        for (int i = 0; i < 2; i++) {
            int row = rb + 32 * i;
            size_t gb = (size_t)row * gi_bstride + jglob;
            gir[i] = gi[gb];
            giz[i] = gi[gb + Hz];
            gin[i] = gi[gb + 2 * Hz];
            hpv[i] = (t > 0)
                ? __bfloat162float(hphi[(size_t)row * Hz + jglob])
                  + __bfloat162float(hplo[(size_t)row * Hz + jglob])
                : 0.f;
        }

        if (t > 0) {
            float acc[3][4];
#pragma unroll
            for (int nt = 0; nt < 3; nt++)
#pragma unroll
                for (int e = 0; e < 4; e++) acc[nt][e] = 0.f;

#define HCP(cc, stg) do {                                                     \
            int kt_ = (cc) * 32;                                              \
            const __nv_bfloat16* src_ = (pseg < 4 ? hphi : hplo)              \
                + (size_t)prow * Hz + kt_ + (pseg & 3) * 8;                   \
            uint32_t dst_ = hsm + (uint32_t)(stg) * HSTAGE + pdst_off;        \
            asm volatile("cp.async.cg.shared.global [%0], [%1], 16;"          \
                         :: "r"(dst_), "l"(src_));                            \
            asm volatile("cp.async.commit_group;" ::: "memory");              \
        } while (0)

            HCP(0, 0);
            HCP(1, 1);

            const int NCH = Hz / 32;
            for (int c = 0; c < NCH; c++) {
                if (c + 1 < NCH)
                    asm volatile("cp.async.wait_group 1;" ::: "memory");
                else
                    asm volatile("cp.async.wait_group 0;" ::: "memory");
                __syncthreads();
                if (c + 2 < NCH) HCP(c + 2, (c + 2) % NSTG);

                const uint32_t hb = hsm + (uint32_t)(c % NSTG) * HSTAGE;
                const int kg = c * 2 + wk;
                uint32_t ahi[4], alo[4], wh4[4], wl4[4], wh2[2], wl2[2];
                ldm_x4(ahi, hb + aoff_hi);
                ldm_x4(alo, hb + aoff_lo);
                ldm_x4(wh4, whis + w4_off + (uint32_t)kg * 32);
                ldm_x2(wh2, whis + w2_off + (uint32_t)kg * 32);
                ldm_x4(wl4, wlos + w4_off + (uint32_t)kg * 32);
                ldm_x2(wl2, wlos + w2_off + (uint32_t)kg * 32);
                mma_16816(acc[0], ahi, &wh4[0]);
                mma_16816(acc[1], ahi, &wh4[2]);
                mma_16816(acc[2], ahi, wh2);
                mma_16816(acc[0], ahi, &wl4[0]);
                mma_16816(acc[1], ahi, &wl4[2]);
                mma_16816(acc[2], ahi, wl2);
                mma_16816(acc[0], alo, &wh4[0]);
                mma_16816(acc[1], alo, &wh4[2]);
                mma_16816(acc[2], alo, wh2);
            }
#undef HCP
            __syncthreads();

            if (wk == 0) {
#pragma unroll
                for (int nt = 0; nt < 3; nt++) {
                    int sc = fcol0 + nt * 8;
                    shg[sc * 65 + frow]           = acc[nt][0];
                    shg[(sc + 1) * 65 + frow]     = acc[nt][1];
                    shg[sc * 65 + frow + 8]       = acc[nt][2];
                    shg[(sc + 1) * 65 + frow + 8] = acc[nt][3];
                }
            }
            __syncthreads();
            if (wk == 1) {
#pragma unroll
                for (int nt = 0; nt < 3; nt++) {
                    int sc = fcol0 + nt * 8;
                    shg[sc * 65 + frow]           += acc[nt][0];
                    shg[(sc + 1) * 65 + frow]     += acc[nt][1];
                    shg[sc * 65 + frow + 8]       += acc[nt][2];
                    shg[(sc + 1) * 65 + frow + 8] += acc[nt][3];
                }
            }
        } else {
            for (int f = tid; f < 48 * 65; f += RTHREADS) shg[f] = 0.f;
        }
        __syncthreads();

#pragma unroll
        for (int i = 0; i < 2; i++) {
            int row = rb + 32 * i;
            float ghr = shg[jj * 65 + row]        + b_r;
            float ghz = shg[(16 + jj) * 65 + row] + b_z;
            float ghn = shg[(32 + jj) * 65 + row] + b_n;

            float rg = 1.f / (1.f + expf(-(gir[i] + ghr)));
            float zg = 1.f / (1.f + expf(-(giz[i] + ghz)));
            float ng = tanhf(gin[i] + rg * ghn);
            float hnew = (1.f - zg) * ng + zg * hpv[i];

            __nv_bfloat16 hb16, lb16;
            split_bf16(hnew, hb16, lb16);
            size_t oo = outoff + (size_t)row * Hz + jglob;
            hhi[oo] = hb16;
            hlo[oo] = lb16;
            if (mode == 1) {
                dout[((size_t)row * Sz + t) * 2048 + (size_t)d * Hz + jglob] = hnew;
                if (t == Sz - 1)
                    dout[(size_t)Bz * Sz * 2048 + (size_t)row * 2048 + (size_t)d * Hz + jglob] = hnew;
            }
        }
        __syncthreads();
    }
}

// ---------------- host launcher (graph-capturable: 8 kernel nodes) ----------------
extern "C" void kernel_launch(void* const* d_in, const int* in_sizes, int n_in,
                              void* d_out, int out_size)
{
    const float* x      = (const float*)d_in[0];
    const float* w_hh0f = (const float*)d_in[2];
    const float* b_hh0f = (const float*)d_in[4];
    const float* w_hh0b = (const float*)d_in[6];
    const float* b_hh0b = (const float*)d_in[8];
    const float* w_hh1f = (const float*)d_in[10];
    const float* b_ih1f = (const float*)d_in[11];
    const float* b_hh1f = (const float*)d_in[12];
    const float* w_hh1b = (const float*)d_in[14];
    const float* b_ih1b = (const float*)d_in[15];
    const float* b_hh1b = (const float*)d_in[16];
    float* out = (float*)d_out;

    float *gi0, *gi1, *b0;
    __nv_bfloat16 *xhi, *xlo, *W0hi, *W0lo, *W1hi, *W1lo, *h0hi, *h0lo, *h1hi, *h1lo;
    cudaGetSymbolAddress((void**)&gi0,  g_gi0);
    cudaGetSymbolAddress((void**)&gi1,  g_gi1);
    cudaGetSymbolAddress((void**)&b0,   g_b0);
    cudaGetSymbolAddress((void**)&xhi,  g_xhi);
    cudaGetSymbolAddress((void**)&xlo,  g_xlo);
    cudaGetSymbolAddress((void**)&W0hi, g_W0hi);
    cudaGetSymbolAddress((void**)&W0lo, g_W0lo);
    cudaGetSymbolAddress((void**)&W1hi, g_W1hi);
    cudaGetSymbolAddress((void**)&W1lo, g_W1lo);
    cudaGetSymbolAddress((void**)&h0hi, g_h0hi);
    cudaGetSymbolAddress((void**)&h0lo, g_h0lo);
    cudaGetSymbolAddress((void**)&h1hi, g_h1hi);
    cudaGetSymbolAddress((void**)&h1lo, g_h1lo);

    cudaFuncSetAttribute(gru_layer_hmma,
                         cudaFuncAttributeMaxDynamicSharedMemorySize, REC_SMEM);
    cudaFuncSetAttribute(gemm_hmma3,
                         cudaFuncAttributeMaxDynamicSharedMemorySize, GEMM_SMEM_BYTES);

    // 1) prep: split/pack GEMM operands to bf16 hi/lo
    prep_w0_split<<<(G3z * INz + 255) / 256, 256>>>(
        (const float*)d_in[1], (const float*)d_in[5],
        (const float*)d_in[3], (const float*)d_in[7]);
    prep_x_split<<<(Bz * Sz * INz + 255) / 256, 256>>>(x);
    prep_w1_split<<<(G3z * Hz + 255) / 256, 256>>>(
        (const float*)d_in[9], (const float*)d_in[13]);

    // 2) gi0 = x @ [W_ih0f ; rev(W_ih0b)]^T + bias
    gemm_hmma3<<<dim3((2 * G3z) / 128, (Bz * Sz) / 128), 256, GEMM_SMEM_BYTES>>>(
        xhi, xlo, INz, W0hi, W0lo, INz, b0, gi0,
        INz, (size_t)Bz * Sz * G3z, G3z);

    // 3) layer-0 recurrence (HMMA, phases 1..511), writes h0 bf16 hi/lo
    gru_layer_hmma<<<NBLK, RTHREADS, REC_SMEM>>>(
        gi0, (size_t)Bz * Sz * G3z, (size_t)G3z, (size_t)Sz * G3z,
        w_hh0f, w_hh0b, b_hh0f, b_hh0b,
        h0hi, h0lo, 0, 0u, nullptr);

    // 4) gi1 = h0_all @ W_ih1^T + bias (per dir)
    for (int dir = 0; dir < 2; dir++) {
        gemm_hmma3<<<dim3(G3z / 128, (Sz * Bz) / 128), 256, GEMM_SMEM_BYTES>>>(
            h0hi + (size_t)dir * Sz * Bz * Hz,
            h0lo + (size_t)dir * Sz * Bz * Hz, Hz,
            W1hi + (size_t)dir * G3z * Hz,
            W1lo + (size_t)dir * G3z * Hz, Hz,
            dir ? b_ih1b : b_ih1f,
            gi1 + (size_t)dir * Sz * Bz * G3z,
            Hz, (size_t)0, G3z);
    }

    // 5) layer-1 recurrence (HMMA, phases 512..1022), writes output
    gru_layer_hmma<<<NBLK, RTHREADS, REC_SMEM>>>(
        gi1, (size_t)Sz * Bz * G3z, (size_t)Bz * G3z, (size_t)G3z,
        w_hh1f, w_hh1b, b_hh1f, b_hh1b,
        h1hi, h1lo, 1, (unsigned)(Sz - 1), out);
}

// round 13
// speedup vs baseline: 3.6665x; 1.0775x over previous
#include <cuda_runtime.h>
#include <cuda_fp16.h>
#include <math.h>
#include <stdint.h>

#define Bz  64
#define Sz  512
#define INz 512
#define Hz  1024
#define G3z 3072
#define NBLK 128

// ---------------- scratch (device globals; no allocation allowed) ----------------
__device__ float g_gi0[(size_t)2 * Bz * Sz * G3z];   // [dir][b][s][n]
__device__ float g_gi1[(size_t)2 * Sz * Bz * G3z];   // [dir][s][b][n]
__device__ float g_b0 [2 * G3z];
__device__ unsigned g_count;
__device__ unsigned g_phase;

// pre-split fp16 operands (hi/lo)
__device__ __align__(16) __half g_xhi [(size_t)Bz * Sz * INz];
__device__ __align__(16) __half g_W0hi[(size_t)2 * G3z * INz];
__device__ __align__(16) __half g_W0lo[(size_t)2 * G3z * INz];
__device__ __align__(16) __half g_W1hi[(size_t)2 * G3z * Hz];
__device__ __align__(16) __half g_W1lo[(size_t)2 * G3z * Hz];
// hidden state, stored ONLY as fp16 hi/lo
__device__ __align__(16) __half g_h0hi[(size_t)2 * Sz * Bz * Hz];
__device__ __align__(16) __half g_h0lo[(size_t)2 * Sz * Bz * Hz];
__device__ __align__(16) __half g_h1hi[(size_t)2 * 2 * Bz * Hz];
__device__ __align__(16) __half g_h1lo[(size_t)2 * 2 * Bz * Hz];

__device__ __forceinline__ uint32_t smem_u32(const void* p) {
    uint32_t a;
    asm("{ .reg .u64 t; cvta.to.shared.u64 t, %1; cvt.u32.u64 %0, t; }" : "=r"(a) : "l"(p));
    return a;
}

__device__ __forceinline__ void split_f16(float v, __half& hi, __half& lo) {
    hi = __float2half_rn(v);
    lo = __float2half_rn(v - __half2float(hi));
}

// ---------------- grid barrier (release/acquire, monotonic phase) -----------------
__device__ __forceinline__ void grid_barrier(unsigned target)
{
    __syncthreads();
    if (threadIdx.x == 0) {
        unsigned old;
        asm volatile("atom.release.gpu.add.u32 %0, [%1], 1;"
                     : "=r"(old) : "l"(&g_count) : "memory");
        if (old == NBLK - 1) {
            g_count = 0;
            asm volatile("red.release.gpu.add.u32 [%0], 1;"
                         :: "l"(&g_phase) : "memory");
        } else {
            unsigned v;
            do {
                asm volatile("ld.acquire.gpu.u32 %0, [%1];"
                             : "=r"(v) : "l"(&g_phase) : "memory");
            } while (v < target);
        }
    }
    __syncthreads();
}

// ---------------- prep: split/pack operands to fp16 hi/lo -------------------------
__global__ void prep_w0_split(const float* __restrict__ wf, const float* __restrict__ wb,
                              const float* __restrict__ bf, const float* __restrict__ bb)
{
    size_t i = (size_t)blockIdx.x * 256 + threadIdx.x;
    size_t total = (size_t)G3z * INz;
    if (i == 0) { g_count = 0; g_phase = 0; }
    if (i < total) {
        size_t n = i / INz, k = i % INz;
        split_f16(wf[i], g_W0hi[i], g_W0lo[i]);
        split_f16(wb[n * INz + (INz - 1 - k)], g_W0hi[total + i], g_W0lo[total + i]);
    }
    if (i < G3z) {
        g_b0[i]       = bf[i];
        g_b0[G3z + i] = bb[i];
    }
}

__global__ void prep_x_split(const float* __restrict__ x)
{
    size_t i = (size_t)blockIdx.x * 256 + threadIdx.x;
    if (i < (size_t)Bz * Sz * INz)
        g_xhi[i] = __float2half_rn(x[i]);
}

__global__ void prep_w1_split(const float* __restrict__ wf, const float* __restrict__ wb)
{
    size_t i = (size_t)blockIdx.x * 256 + threadIdx.x;
    size_t total = (size_t)G3z * Hz;
    if (i < total) {
        split_f16(wf[i], g_W1hi[i], g_W1lo[i]);
        split_f16(wb[i], g_W1hi[total + i], g_W1lo[total + i]);
    }
}

// ================ shared HMMA primitives ================
__device__ __forceinline__ void ldm_x4(uint32_t* r, uint32_t addr) {
    asm volatile("ldmatrix.sync.aligned.m8n8.x4.shared.b16 {%0,%1,%2,%3}, [%4];"
                 : "=r"(r[0]), "=r"(r[1]), "=r"(r[2]), "=r"(r[3]) : "r"(addr));
}
__device__ __forceinline__ void ldm_x2(uint32_t* r, uint32_t addr) {
    asm volatile("ldmatrix.sync.aligned.m8n8.x2.shared.b16 {%0,%1}, [%2];"
                 : "=r"(r[0]), "=r"(r[1]) : "r"(addr));
}
__device__ __forceinline__ void mma_f16(float* c, const uint32_t* a, const uint32_t* b) {
    asm volatile(
        "mma.sync.aligned.m16n8k16.row.col.f32.f16.f16.f32 "
        "{%0,%1,%2,%3}, {%4,%5,%6,%7}, {%8,%9}, {%0,%1,%2,%3};"
        : "+f"(c[0]), "+f"(c[1]), "+f"(c[2]), "+f"(c[3])
        : "r"(a[0]), "r"(a[1]), "r"(a[2]), "r"(a[3]), "r"(b[0]), "r"(b[1]));
}

// ================ HMMA split-fp16 GEMM v4: C = A @ W^T + bias ================
// 2-pass: Ahi*Bhi + Ahi*Blo (A quantized to fp16; W split hi/lo).
// Swizzled unpadded tiles (128 rows x 64B), 4-stage cp.async, one sync/chunk.
#define GT_BYTES 8192                       // one operand tile: 128 x 32 fp16
#define GS_BYTES (3 * GT_BYTES)             // Ahi, Bhi, Blo = 24576
#define GNSTG 4
#define GEMM_SMEM_BYTES (GNSTG * GS_BYTES)  // 98304 -> 2 CTAs/SM

__global__ void __launch_bounds__(256, 2) gemm_hmma4(
    const __half* __restrict__ Ahi, int lda,
    const __half* __restrict__ Bhi, const __half* __restrict__ Blo, int ldw,
    const float* __restrict__ bias,
    float* __restrict__ C,
    int K, size_t dirStride, int N0)
{
    extern __shared__ char sm[];
    const int tid = threadIdx.x, lane = tid & 31, wid = tid >> 5;
    const int wm = wid >> 2, wn = wid & 3;
    const int bn = blockIdx.x, bm = blockIdx.y;

    const __half* Ahi_b = Ahi + (size_t)bm * 128 * lda;
    const __half* Bhi_b = Bhi + (size_t)bn * 128 * ldw;
    const __half* Blo_b = Blo + (size_t)bn * 128 * ldw;

    float acc[4][4][4];
#pragma unroll
    for (int mi = 0; mi < 4; mi++)
#pragma unroll
        for (int ni = 0; ni < 4; ni++)
#pragma unroll
            for (int e = 0; e < 4; e++) acc[mi][ni][e] = 0.f;

    const int NC = K / 32;
    const uint32_t smb = smem_u32(sm);

    // per-thread fragment address precomputation (swizzled 64B rows)
    const int half_a = lane >> 4;
    const int half_b = (lane >> 3) & 1;
    uint32_t a_b64[4], b_b64[2];
    int a_q[4], b_q[2];
#pragma unroll
    for (int mi = 0; mi < 4; mi++) {
        int row = wm * 64 + (lane & 15) + mi * 16;
        a_b64[mi] = (uint32_t)row * 64;
        a_q[mi] = (row >> 1) & 3;
    }
#pragma unroll
    for (int nj = 0; nj < 2; nj++) {
        int row = wn * 32 + (lane & 7) + ((lane >> 4) & 1) * 8 + nj * 16;
        b_b64[nj] = (uint32_t)row * 64;
        b_q[nj] = (row >> 1) & 3;
    }

#define CP_PREFETCH(cc, stg) do {                                             \
        int kt_ = (cc) * 32;                                                  \
        uint32_t base_ = smb + (uint32_t)(stg) * GS_BYTES;                    \
        _Pragma("unroll")                                                     \
        for (int i_ = 0; i_ < 6; i_++) {                                      \
            int line_ = tid + 256 * i_;                                       \
            int tile_ = line_ >> 9;                                           \
            int idx_  = line_ & 511;                                          \
            int row_  = idx_ >> 2;                                            \
            int seg_  = idx_ & 3;                                             \
            const __half* src_;                                               \
            if (tile_ == 0)      src_ = Ahi_b + (size_t)row_ * lda + kt_ + seg_ * 8; \
            else if (tile_ == 1) src_ = Bhi_b + (size_t)row_ * ldw + kt_ + seg_ * 8; \
            else                 src_ = Blo_b + (size_t)row_ * ldw + kt_ + seg_ * 8; \
            uint32_t dst_ = base_ + (uint32_t)tile_ * GT_BYTES                \
                            + (uint32_t)row_ * 64                             \
                            + (uint32_t)(((seg_ ^ ((row_ >> 1) & 3))) << 4);  \
            asm volatile("cp.async.cg.shared.global [%0], [%1], 16;"          \
                         :: "r"(dst_), "l"(src_));                            \
        }                                                                     \
        asm volatile("cp.async.commit_group;" ::: "memory");                  \
    } while (0)

    CP_PREFETCH(0, 0);
    CP_PREFETCH(1, 1);
    CP_PREFETCH(2, 2);

    for (int c = 0; c < NC; c++) {
        if (c + 2 < NC)
            asm volatile("cp.async.wait_group 2;" ::: "memory");
        else if (c + 1 < NC)
            asm volatile("cp.async.wait_group 1;" ::: "memory");
        else
            asm volatile("cp.async.wait_group 0;" ::: "memory");
        __syncthreads();
        if (c + 3 < NC) CP_PREFETCH(c + 3, (c + 3) & 3);

        const uint32_t st = smb + (uint32_t)(c & 3) * GS_BYTES;
#pragma unroll
        for (int kh = 0; kh < 2; kh++) {
            uint32_t afr[4][4], bhi[2][4], blo[2][4];
            const uint32_t sa = (uint32_t)(2 * kh + half_a);
            const uint32_t sb = (uint32_t)(2 * kh + half_b);
#pragma unroll
            for (int mi = 0; mi < 4; mi++)
                ldm_x4(afr[mi], st + a_b64[mi] + ((sa ^ a_q[mi]) << 4));
#pragma unroll
            for (int nj = 0; nj < 2; nj++) {
                ldm_x4(bhi[nj], st + 1u * GT_BYTES + b_b64[nj] + ((sb ^ b_q[nj]) << 4));
                ldm_x4(blo[nj], st + 2u * GT_BYTES + b_b64[nj] + ((sb ^ b_q[nj]) << 4));
            }
#pragma unroll
            for (int mi = 0; mi < 4; mi++)
#pragma unroll
                for (int ni = 0; ni < 4; ni++) {
                    mma_f16(acc[mi][ni], afr[mi], &bhi[ni >> 1][(ni & 1) * 2]);
                    mma_f16(acc[mi][ni], afr[mi], &blo[ni >> 1][(ni & 1) * 2]);
                }
        }
    }
#undef CP_PREFETCH

    // epilogue: add bias, scatter to packed-dir layout
    const int grow = lane >> 2;
    const int gcol = (lane & 3) * 2;
    const int nbase = bn * 128;
    const int dir = nbase / N0;
    const int nn_base = nbase - dir * N0;
    float* Cd = C + (size_t)dir * dirStride;

#pragma unroll
    for (int mi = 0; mi < 4; mi++) {
        size_t m0 = (size_t)bm * 128 + wm * 64 + mi * 16 + grow;
#pragma unroll
        for (int ni = 0; ni < 4; ni++) {
            int nloc = wn * 32 + ni * 8 + gcol;
            float bx = __ldg(&bias[nbase + nloc]);
            float by = __ldg(&bias[nbase + nloc + 1]);
            float2 v0 = make_float2(acc[mi][ni][0] + bx, acc[mi][ni][1] + by);
            float2 v1 = make_float2(acc[mi][ni][2] + bx, acc[mi][ni][3] + by);
            *(float2*)(Cd + m0 * G3z + nn_base + nloc)       = v0;
            *(float2*)(Cd + (m0 + 8) * G3z + nn_base + nloc) = v1;
        }
    }
}

// ================ persistent HMMA recurrent layer (fp16 3-pass, R10 structure) =====
#define LDW  1032
#define WT_BYTES (48 * LDW * 2)
#define HSTAGE 8192
#define NSTG 3
#define REC_SMEM (2 * WT_BYTES + NSTG * HSTAGE)
#define RTHREADS 512

__global__ void __launch_bounds__(RTHREADS) gru_layer_hmma(
    const float* __restrict__ gi_base, size_t gi_dstride, size_t gi_tstride, size_t gi_bstride,
    const float* __restrict__ whf, const float* __restrict__ whb,
    const float* __restrict__ bhf, const float* __restrict__ bhb,
    __half* __restrict__ hhi, __half* __restrict__ hlo,
    int mode, unsigned phase_base, float* __restrict__ dout)
{
    extern __shared__ char sm[];
    __half* Whi = (__half*)sm;
    __half* Wlo = (__half*)(sm + WT_BYTES);
    float* shg = (float*)(sm + 2 * WT_BYTES);
    const uint32_t whis = smem_u32(Whi);
    const uint32_t wlos = smem_u32(Wlo);
    const uint32_t hsm  = smem_u32(sm + 2 * WT_BYTES);

    const int d  = blockIdx.x >> 6;
    const int jg = blockIdx.x & 63;
    const int tid = threadIdx.x, lane = tid & 31, wid = tid >> 5;
    const int wk = wid >> 3;
    const int wq = wid & 7;
    const int wm = wq & 3, wn = wq >> 2;

    const float* w  = d ? whb : whf;
    const float* bh = d ? bhb : bhf;

    for (int f = tid; f < 48 * 256; f += RTHREADS) {
        int sr = f >> 8;
        int k4 = (f & 255) * 4;
        const float* src = w + (size_t)((sr >> 4) * Hz + jg * 16 + (sr & 15)) * Hz + k4;
        float4 v = *(const float4*)src;
        __half h0, l0, h1, l1, h2, l2, h3, l3;
        split_f16(v.x, h0, l0); split_f16(v.y, h1, l1);
        split_f16(v.z, h2, l2); split_f16(v.w, h3, l3);
        __half* ph = Whi + sr * LDW + k4;
        __half* pl = Wlo + sr * LDW + k4;
        ph[0] = h0; ph[1] = h1; ph[2] = h2; ph[3] = h3;
        pl[0] = l0; pl[1] = l1; pl[2] = l2; pl[3] = l3;
    }

    const int jj = tid & 15;
    const int rb = tid >> 4;
    const int jglob = jg * 16 + jj;
    const float b_r = __ldg(&bh[jglob]);
    const float b_z = __ldg(&bh[Hz + jglob]);
    const float b_n = __ldg(&bh[2 * Hz + jglob]);
    __syncthreads();

    const uint32_t w4_off = (uint32_t)(wn * 24 + (lane & 7) + ((lane >> 4) & 1) * 8) * (LDW * 2)
                            + ((lane >> 3) & 1) * 16;
    const uint32_t w2_off = (uint32_t)(wn * 24 + 16 + (lane & 7)) * (LDW * 2)
                            + ((lane >> 3) & 1) * 16;
    const int arow  = wm * 16 + (lane & 15);
    const int ahalf = lane >> 4;
    const uint32_t aoff_hi = (uint32_t)(arow * 128 + (((wk * 2 + ahalf)     ^ (arow & 7)) * 16));
    const uint32_t aoff_lo = (uint32_t)(arow * 128 + (((4 + wk * 2 + ahalf) ^ (arow & 7)) * 16));
    const int prow = tid >> 3;
    const int pseg = tid & 7;
    const uint32_t pdst_off = (uint32_t)(prow * 128 + ((pseg ^ (prow & 7)) * 16));
    const int frow = wm * 16 + (lane >> 2);
    const int fcol0 = wn * 24 + (lane & 3) * 2;

    for (int t = 0; t < Sz; t++) {
        if (t > 0) grid_barrier(phase_base + (unsigned)t);

        size_t prevoff, outoff;
        if (mode == 0) {
            prevoff = ((size_t)d * Sz + (size_t)(t > 0 ? t - 1 : 0)) * Bz * Hz;
            outoff  = ((size_t)d * Sz + t) * Bz * Hz;
        } else {
            int cur = t & 1;
            prevoff = ((size_t)cur * 2 + d) * Bz * Hz;
            outoff  = ((size_t)(cur ^ 1) * 2 + d) * Bz * Hz;
        }
        const __half* hphi = hhi + prevoff;
        const __half* hplo = hlo + prevoff;
        const float* gi = gi_base + (size_t)d * gi_dstride + (size_t)t * gi_tstride;

        float gir[2], giz[2], gin[2], hpv[2];
#pragma unroll
        for (int i = 0; i < 2; i++) {
            int row = rb + 32 * i;
            size_t gb = (size_t)row * gi_bstride + jglob;
            gir[i] = gi[gb];
            giz[i] = gi[gb + Hz];
            gin[i] = gi[gb + 2 * Hz];
            hpv[i] = (t > 0)
                ? __half2float(hphi[(size_t)row * Hz + jglob])
                  + __half2float(hplo[(size_t)row * Hz + jglob])
                : 0.f;
        }

        if (t > 0) {
            float acc[3][4];
#pragma unroll
            for (int nt = 0; nt < 3; nt++)
#pragma unroll
                for (int e = 0; e < 4; e++) acc[nt][e] = 0.f;

#define HCP(cc, stg) do {                                                     \
            int kt_ = (cc) * 32;                                              \
            const __half* src_ = (pseg < 4 ? hphi : hplo)                     \
                + (size_t)prow * Hz + kt_ + (pseg & 3) * 8;                   \
            uint32_t dst_ = hsm + (uint32_t)(stg) * HSTAGE + pdst_off;        \
            asm volatile("cp.async.cg.shared.global [%0], [%1], 16;"          \
                         :: "r"(dst_), "l"(src_));                            \
            asm volatile("cp.async.commit_group;" ::: "memory");              \
        } while (0)

            HCP(0, 0);
            HCP(1, 1);

            const int NCH = Hz / 32;
            for (int c = 0; c < NCH; c++) {
                if (c + 1 < NCH)
                    asm volatile("cp.async.wait_group 1;" ::: "memory");
                else
                    asm volatile("cp.async.wait_group 0;" ::: "memory");
                __syncthreads();
                if (c + 2 < NCH) HCP(c + 2, (c + 2) % NSTG);

                const uint32_t hb = hsm + (uint32_t)(c % NSTG) * HSTAGE;
                const int kg = c * 2 + wk;
                uint32_t ahi[4], alo[4], wh4[4], wl4[4], wh2[2], wl2[2];
                ldm_x4(ahi, hb + aoff_hi);
                ldm_x4(alo, hb + aoff_lo);
                ldm_x4(wh4, whis + w4_off + (uint32_t)kg * 32);
                ldm_x2(wh2, whis + w2_off + (uint32_t)kg * 32);
                ldm_x4(wl4, wlos + w4_off + (uint32_t)kg * 32);
                ldm_x2(wl2, wlos + w2_off + (uint32_t)kg * 32);
                mma_f16(acc[0], ahi, &wh4[0]);
                mma_f16(acc[1], ahi, &wh4[2]);
                mma_f16(acc[2], ahi, wh2);
                mma_f16(acc[0], ahi, &wl4[0]);
                mma_f16(acc[1], ahi, &wl4[2]);
                mma_f16(acc[2], ahi, wl2);
                mma_f16(acc[0], alo, &wh4[0]);
                mma_f16(acc[1], alo, &wh4[2]);
                mma_f16(acc[2], alo, wh2);
            }
#undef HCP
            __syncthreads();

            if (wk == 0) {
#pragma unroll
                for (int nt = 0; nt < 3; nt++) {
                    int sc = fcol0 + nt * 8;
                    shg[sc * 65 + frow]           = acc[nt][0];
                    shg[(sc + 1) * 65 + frow]     = acc[nt][1];
                    shg[sc * 65 + frow + 8]       = acc[nt][2];
                    shg[(sc + 1) * 65 + frow + 8] = acc[nt][3];
                }
            }
            __syncthreads();
            if (wk == 1) {
#pragma unroll
                for (int nt = 0; nt < 3; nt++) {
                    int sc = fcol0 + nt * 8;
                    shg[sc * 65 + frow]           += acc[nt][0];
                    shg[(sc + 1) * 65 + frow]     += acc[nt][1];
                    shg[sc * 65 + frow + 8]       += acc[nt][2];
                    shg[(sc + 1) * 65 + frow + 8] += acc[nt][3];
                }
            }
        } else {
            for (int f = tid; f < 48 * 65; f += RTHREADS) shg[f] = 0.f;
        }
        __syncthreads();

#pragma unroll
        for (int i = 0; i < 2; i++) {
            int row = rb + 32 * i;
            float ghr = shg[jj * 65 + row]        + b_r;
            float ghz = shg[(16 + jj) * 65 + row] + b_z;
            float ghn = shg[(32 + jj) * 65 + row] + b_n;

            float rg = 1.f / (1.f + expf(-(gir[i] + ghr)));
            float zg = 1.f / (1.f + expf(-(giz[i] + ghz)));
            float ng = tanhf(gin[i] + rg * ghn);
            float hnew = (1.f - zg) * ng + zg * hpv[i];

            __half hb16, lb16;
            split_f16(hnew, hb16, lb16);
            size_t oo = outoff + (size_t)row * Hz + jglob;
            hhi[oo] = hb16;
            hlo[oo] = lb16;
            if (mode == 1) {
                dout[((size_t)row * Sz + t) * 2048 + (size_t)d * Hz + jglob] = hnew;
                if (t == Sz - 1)
                    dout[(size_t)Bz * Sz * 2048 + (size_t)row * 2048 + (size_t)d * Hz + jglob] = hnew;
            }
        }
        __syncthreads();
    }
}

// ---------------- host launcher (graph-capturable: 8 kernel nodes) ----------------
extern "C" void kernel_launch(void* const* d_in, const int* in_sizes, int n_in,
                              void* d_out, int out_size)
{
    const float* x      = (const float*)d_in[0];
    const float* w_hh0f = (const float*)d_in[2];
    const float* b_hh0f = (const float*)d_in[4];
    const float* w_hh0b = (const float*)d_in[6];
    const float* b_hh0b = (const float*)d_in[8];
    const float* w_hh1f = (const float*)d_in[10];
    const float* b_ih1f = (const float*)d_in[11];
    const float* b_hh1f = (const float*)d_in[12];
    const float* w_hh1b = (const float*)d_in[14];
    const float* b_ih1b = (const float*)d_in[15];
    const float* b_hh1b = (const float*)d_in[16];
    float* out = (float*)d_out;

    float *gi0, *gi1, *b0;
    __half *xhi, *W0hi, *W0lo, *W1hi, *W1lo, *h0hi, *h0lo, *h1hi, *h1lo;
    cudaGetSymbolAddress((void**)&gi0,  g_gi0);
    cudaGetSymbolAddress((void**)&gi1,  g_gi1);
    cudaGetSymbolAddress((void**)&b0,   g_b0);
    cudaGetSymbolAddress((void**)&xhi,  g_xhi);
    cudaGetSymbolAddress((void**)&W0hi, g_W0hi);
    cudaGetSymbolAddress((void**)&W0lo, g_W0lo);
    cudaGetSymbolAddress((void**)&W1hi, g_W1hi);
    cudaGetSymbolAddress((void**)&W1lo, g_W1lo);
    cudaGetSymbolAddress((void**)&h0hi, g_h0hi);
    cudaGetSymbolAddress((void**)&h0lo, g_h0lo);
    cudaGetSymbolAddress((void**)&h1hi, g_h1hi);
    cudaGetSymbolAddress((void**)&h1lo, g_h1lo);

    cudaFuncSetAttribute(gru_layer_hmma,
                         cudaFuncAttributeMaxDynamicSharedMemorySize, REC_SMEM);
    cudaFuncSetAttribute(gemm_hmma4,
                         cudaFuncAttributeMaxDynamicSharedMemorySize, GEMM_SMEM_BYTES);

    // 1) prep: split/pack GEMM operands to fp16 hi/lo
    prep_w0_split<<<(G3z * INz + 255) / 256, 256>>>(
        (const float*)d_in[1], (const float*)d_in[5],
        (const float*)d_in[3], (const float*)d_in[7]);
    prep_x_split<<<(Bz * Sz * INz + 255) / 256, 256>>>(x);
    prep_w1_split<<<(G3z * Hz + 255) / 256, 256>>>(
        (const float*)d_in[9], (const float*)d_in[13]);

    // 2) gi0 = x @ [W_ih0f ; rev(W_ih0b)]^T + bias  (2-pass split-fp16)
    gemm_hmma4<<<dim3((2 * G3z) / 128, (Bz * Sz) / 128), 256, GEMM_SMEM_BYTES>>>(
        xhi, INz, W0hi, W0lo, INz, b0, gi0,
        INz, (size_t)Bz * Sz * G3z, G3z);

    // 3) layer-0 recurrence (fp16 3-pass HMMA, phases 1..511)
    gru_layer_hmma<<<NBLK, RTHREADS, REC_SMEM>>>(
        gi0, (size_t)Bz * Sz * G3z, (size_t)G3z, (size_t)Sz * G3z,
        w_hh0f, w_hh0b, b_hh0f, b_hh0b,
        h0hi, h0lo, 0, 0u, nullptr);

    // 4) gi1 = h0_all @ W_ih1^T + bias (2-pass split-fp16, per dir; reads h0hi only)
    for (int dir = 0; dir < 2; dir++) {
        gemm_hmma4<<<dim3(G3z / 128, (Sz * Bz) / 128), 256, GEMM_SMEM_BYTES>>>(
            h0hi + (size_t)dir * Sz * Bz * Hz, Hz,
            W1hi + (size_t)dir * G3z * Hz,
            W1lo + (size_t)dir * G3z * Hz, Hz,
            dir ? b_ih1b : b_ih1f,
            gi1 + (size_t)dir * Sz * Bz * G3z,
            Hz, (size_t)0, G3z);
    }

    // 5) layer-1 recurrence (fp16 3-pass HMMA, phases 512..1022), writes output
    gru_layer_hmma<<<NBLK, RTHREADS, REC_SMEM>>>(
        gi1, (size_t)Sz * Bz * G3z, (size_t)Bz * G3z, (size_t)G3z,
        w_hh1f, w_hh1b, b_hh1f, b_hh1b,
        h1hi, h1lo, 1, (unsigned)(Sz - 1), out);
}

// round 15
// speedup vs baseline: 4.3579x; 1.1886x over previous
#include <cuda_runtime.h>
#include <cuda_fp16.h>
#include <math.h>
#include <stdint.h>

#define Bz  64
#define Sz  512
#define INz 512
#define Hz  1024
#define G3z 3072
#define NBLK 128

// ---------------- scratch (device globals; no allocation allowed) ----------------
__device__ float g_gi0[(size_t)2 * Bz * Sz * G3z];   // [dir][b][s][n]
__device__ float g_gi1[(size_t)2 * Sz * Bz * G3z];   // [dir][s][b][n]
__device__ float g_b0 [2 * G3z];
__device__ unsigned g_count;
__device__ unsigned g_phase;

// pre-split fp16 operands (hi/lo)
__device__ __align__(16) __half g_xhi [(size_t)Bz * Sz * INz];
__device__ __align__(16) __half g_W0hi[(size_t)2 * G3z * INz];
__device__ __align__(16) __half g_W0lo[(size_t)2 * G3z * INz];
__device__ __align__(16) __half g_W1hi[(size_t)2 * G3z * Hz];
__device__ __align__(16) __half g_W1lo[(size_t)2 * G3z * Hz];
// hidden state, stored ONLY as fp16 hi/lo
__device__ __align__(16) __half g_h0hi[(size_t)2 * Sz * Bz * Hz];
__device__ __align__(16) __half g_h0lo[(size_t)2 * Sz * Bz * Hz];
__device__ __align__(16) __half g_h1hi[(size_t)2 * 2 * Bz * Hz];
__device__ __align__(16) __half g_h1lo[(size_t)2 * 2 * Bz * Hz];

__device__ __forceinline__ uint32_t smem_u32(const void* p) {
    uint32_t a;
    asm("{ .reg .u64 t; cvta.to.shared.u64 t, %1; cvt.u32.u64 %0, t; }" : "=r"(a) : "l"(p));
    return a;
}

__device__ __forceinline__ void split_f16(float v, __half& hi, __half& lo) {
    hi = __float2half_rn(v);
    lo = __float2half_rn(v - __half2float(hi));
}

// ---------------- grid barrier (release/acquire, monotonic phase) -----------------
__device__ __forceinline__ void grid_barrier(unsigned target)
{
    __syncthreads();
    if (threadIdx.x == 0) {
        unsigned old;
        asm volatile("atom.release.gpu.add.u32 %0, [%1], 1;"
                     : "=r"(old) : "l"(&g_count) : "memory");
        if (old == NBLK - 1) {
            g_count = 0;
            asm volatile("red.release.gpu.add.u32 [%0], 1;"
                         :: "l"(&g_phase) : "memory");
        } else {
            unsigned v;
            do {
                asm volatile("ld.acquire.gpu.u32 %0, [%1];"
                             : "=r"(v) : "l"(&g_phase) : "memory");
            } while (v < target);
        }
    }
    __syncthreads();
}

// ---------------- prep: split/pack operands to fp16 hi/lo -------------------------
__global__ void prep_w0_split(const float* __restrict__ wf, const float* __restrict__ wb,
                              const float* __restrict__ bf, const float* __restrict__ bb)
{
    size_t i = (size_t)blockIdx.x * 256 + threadIdx.x;
    size_t total = (size_t)G3z * INz;
    if (i == 0) { g_count = 0; g_phase = 0; }
    if (i < total) {
        size_t n = i / INz, k = i % INz;
        split_f16(wf[i], g_W0hi[i], g_W0lo[i]);
        split_f16(wb[n * INz + (INz - 1 - k)], g_W0hi[total + i], g_W0lo[total + i]);
    }
    if (i < G3z) {
        g_b0[i]       = bf[i];
        g_b0[G3z + i] = bb[i];
    }
}

__global__ void prep_x_split(const float* __restrict__ x)
{
    size_t i = (size_t)blockIdx.x * 256 + threadIdx.x;
    if (i < (size_t)Bz * Sz * INz)
        g_xhi[i] = __float2half_rn(x[i]);
}

__global__ void prep_w1_split(const float* __restrict__ wf, const float* __restrict__ wb)
{
    size_t i = (size_t)blockIdx.x * 256 + threadIdx.x;
    size_t total = (size_t)G3z * Hz;
    if (i < total) {
        split_f16(wf[i], g_W1hi[i], g_W1lo[i]);
        split_f16(wb[i], g_W1hi[total + i], g_W1lo[total + i]);
    }
}

// ================ shared HMMA primitives ================
__device__ __forceinline__ void ldm_x4(uint32_t* r, uint32_t addr) {
    asm volatile("ldmatrix.sync.aligned.m8n8.x4.shared.b16 {%0,%1,%2,%3}, [%4];"
                 : "=r"(r[0]), "=r"(r[1]), "=r"(r[2]), "=r"(r[3]) : "r"(addr));
}
__device__ __forceinline__ void ldm_x2(uint32_t* r, uint32_t addr) {
    asm volatile("ldmatrix.sync.aligned.m8n8.x2.shared.b16 {%0,%1}, [%2];"
                 : "=r"(r[0]), "=r"(r[1]) : "r"(addr));
}
__device__ __forceinline__ void mma_f16(float* c, const uint32_t* a, const uint32_t* b) {
    asm volatile(
        "mma.sync.aligned.m16n8k16.row.col.f32.f16.f16.f32 "
        "{%0,%1,%2,%3}, {%4,%5,%6,%7}, {%8,%9}, {%0,%1,%2,%3};"
        : "+f"(c[0]), "+f"(c[1]), "+f"(c[2]), "+f"(c[3])
        : "r"(a[0]), "r"(a[1]), "r"(a[2]), "r"(a[3]), "r"(b[0]), "r"(b[1]));
}

// ================ HMMA split-fp16 GEMM v4 (unchanged R13) ================
#define GT_BYTES 8192
#define GS_BYTES (3 * GT_BYTES)
#define GNSTG 4
#define GEMM_SMEM_BYTES (GNSTG * GS_BYTES)

__global__ void __launch_bounds__(256, 2) gemm_hmma4(
    const __half* __restrict__ Ahi, int lda,
    const __half* __restrict__ Bhi, const __half* __restrict__ Blo, int ldw,
    const float* __restrict__ bias,
    float* __restrict__ C,
    int K, size_t dirStride, int N0)
{
    extern __shared__ char sm[];
    const int tid = threadIdx.x, lane = tid & 31, wid = tid >> 5;
    const int wm = wid >> 2, wn = wid & 3;
    const int bn = blockIdx.x, bm = blockIdx.y;

    const __half* Ahi_b = Ahi + (size_t)bm * 128 * lda;
    const __half* Bhi_b = Bhi + (size_t)bn * 128 * ldw;
    const __half* Blo_b = Blo + (size_t)bn * 128 * ldw;

    float acc[4][4][4];
#pragma unroll
    for (int mi = 0; mi < 4; mi++)
#pragma unroll
        for (int ni = 0; ni < 4; ni++)
#pragma unroll
            for (int e = 0; e < 4; e++) acc[mi][ni][e] = 0.f;

    const int NC = K / 32;
    const uint32_t smb = smem_u32(sm);

    const int half_a = lane >> 4;
    const int half_b = (lane >> 3) & 1;
    uint32_t a_b64[4], b_b64[2];
    int a_q[4], b_q[2];
#pragma unroll
    for (int mi = 0; mi < 4; mi++) {
        int row = wm * 64 + (lane & 15) + mi * 16;
        a_b64[mi] = (uint32_t)row * 64;
        a_q[mi] = (row >> 1) & 3;
    }
#pragma unroll
    for (int nj = 0; nj < 2; nj++) {
        int row = wn * 32 + (lane & 7) + ((lane >> 4) & 1) * 8 + nj * 16;
        b_b64[nj] = (uint32_t)row * 64;
        b_q[nj] = (row >> 1) & 3;
    }

#define CP_PREFETCH(cc, stg) do {                                             \
        int kt_ = (cc) * 32;                                                  \
        uint32_t base_ = smb + (uint32_t)(stg) * GS_BYTES;                    \
        _Pragma("unroll")                                                     \
        for (int i_ = 0; i_ < 6; i_++) {                                      \
            int line_ = tid + 256 * i_;                                       \
            int tile_ = line_ >> 9;                                           \
            int idx_  = line_ & 511;                                          \
            int row_  = idx_ >> 2;                                            \
            int seg_  = idx_ & 3;                                             \
            const __half* src_;                                               \
            if (tile_ == 0)      src_ = Ahi_b + (size_t)row_ * lda + kt_ + seg_ * 8; \
            else if (tile_ == 1) src_ = Bhi_b + (size_t)row_ * ldw + kt_ + seg_ * 8; \
            else                 src_ = Blo_b + (size_t)row_ * ldw + kt_ + seg_ * 8; \
            uint32_t dst_ = base_ + (uint32_t)tile_ * GT_BYTES                \
                            + (uint32_t)row_ * 64                             \
                            + (uint32_t)(((seg_ ^ ((row_ >> 1) & 3))) << 4);  \
            asm volatile("cp.async.cg.shared.global [%0], [%1], 16;"          \
                         :: "r"(dst_), "l"(src_));                            \
        }                                                                     \
        asm volatile("cp.async.commit_group;" ::: "memory");                  \
    } while (0)

    CP_PREFETCH(0, 0);
    CP_PREFETCH(1, 1);
    CP_PREFETCH(2, 2);

    for (int c = 0; c < NC; c++) {
        if (c + 2 < NC)
            asm volatile("cp.async.wait_group 2;" ::: "memory");
        else if (c + 1 < NC)
            asm volatile("cp.async.wait_group 1;" ::: "memory");
        else
            asm volatile("cp.async.wait_group 0;" ::: "memory");
        __syncthreads();
        if (c + 3 < NC) CP_PREFETCH(c + 3, (c + 3) & 3);

        const uint32_t st = smb + (uint32_t)(c & 3) * GS_BYTES;
#pragma unroll
        for (int kh = 0; kh < 2; kh++) {
            uint32_t afr[4][4], bhi[2][4], blo[2][4];
            const uint32_t sa = (uint32_t)(2 * kh + half_a);
            const uint32_t sb = (uint32_t)(2 * kh + half_b);
#pragma unroll
            for (int mi = 0; mi < 4; mi++)
                ldm_x4(afr[mi], st + a_b64[mi] + ((sa ^ a_q[mi]) << 4));
#pragma unroll
            for (int nj = 0; nj < 2; nj++) {
                ldm_x4(bhi[nj], st + 1u * GT_BYTES + b_b64[nj] + ((sb ^ b_q[nj]) << 4));
                ldm_x4(blo[nj], st + 2u * GT_BYTES + b_b64[nj] + ((sb ^ b_q[nj]) << 4));
            }
#pragma unroll
            for (int mi = 0; mi < 4; mi++)
#pragma unroll
                for (int ni = 0; ni < 4; ni++) {
                    mma_f16(acc[mi][ni], afr[mi], &bhi[ni >> 1][(ni & 1) * 2]);
                    mma_f16(acc[mi][ni], afr[mi], &blo[ni >> 1][(ni & 1) * 2]);
                }
        }
    }
#undef CP_PREFETCH

    const int grow = lane >> 2;
    const int gcol = (lane & 3) * 2;
    const int nbase = bn * 128;
    const int dir = nbase / N0;
    const int nn_base = nbase - dir * N0;
    float* Cd = C + (size_t)dir * dirStride;

#pragma unroll
    for (int mi = 0; mi < 4; mi++) {
        size_t m0 = (size_t)bm * 128 + wm * 64 + mi * 16 + grow;
#pragma unroll
        for (int ni = 0; ni < 4; ni++) {
            int nloc = wn * 32 + ni * 8 + gcol;
            float bx = __ldg(&bias[nbase + nloc]);
            float by = __ldg(&bias[nbase + nloc + 1]);
            float2 v0 = make_float2(acc[mi][ni][0] + bx, acc[mi][ni][1] + by);
            float2 v1 = make_float2(acc[mi][ni][2] + bx, acc[mi][ni][3] + by);
            *(float2*)(Cd + m0 * G3z + nn_base + nloc)       = v0;
            *(float2*)(Cd + (m0 + 8) * G3z + nn_base + nloc) = v1;
        }
    }
}

// ================ persistent HMMA recurrent layer v2 ===============================
// W_hh quantized to single fp16 in smem (99KB); 2-pass (Ahi*W + Alo*W) keeps h
// state split. K-chunks of 64 (16KB stages, 3-stage pipeline, 16 syncs/step).
// 16 warps: wk = wid>>3 (k half of chunk); wq = wid&7: wm = wq&3, wn = wq>>2.
#define LDW  1032
#define WT_BYTES (48 * LDW * 2)         // 99072 (single fp16 W)
#define HSTAGE 16384                    // 64 rows x 256B (hi 128B | lo 128B)
#define NSTG 3
#define REC_SMEM (WT_BYTES + NSTG * HSTAGE)   // 148224
#define RTHREADS 512

__global__ void __launch_bounds__(RTHREADS) gru_layer_hmma(
    const float* __restrict__ gi_base, size_t gi_dstride, size_t gi_tstride, size_t gi_bstride,
    const float* __restrict__ whf, const float* __restrict__ whb,
    const float* __restrict__ bhf, const float* __restrict__ bhb,
    __half* __restrict__ hhi, __half* __restrict__ hlo,
    int mode, unsigned phase_base, float* __restrict__ dout)
{
    extern __shared__ char sm[];
    __half* Wsm = (__half*)sm;
    float* shg = (float*)(sm + WT_BYTES);            // aliases h stages (post-MMA)
    const uint32_t wsms = smem_u32(Wsm);
    const uint32_t hsm  = smem_u32(sm + WT_BYTES);

    const int d  = blockIdx.x >> 6;
    const int jg = blockIdx.x & 63;
    const int tid = threadIdx.x, lane = tid & 31, wid = tid >> 5;
    const int wk = wid >> 3;
    const int wq = wid & 7;
    const int wm = wq & 3, wn = wq >> 2;

    const float* w  = d ? whb : whf;
    const float* bh = d ? bhb : bhf;

    // one-time: quantize this CTA's W slice (48 x 1024) to fp16 in smem
    for (int f = tid; f < 48 * 256; f += RTHREADS) {
        int sr = f >> 8;
        int k4 = (f & 255) * 4;
        const float* src = w + (size_t)((sr >> 4) * Hz + jg * 16 + (sr & 15)) * Hz + k4;
        float4 v = *(const float4*)src;
        __half* ph = Wsm + sr * LDW + k4;
        ph[0] = __float2half_rn(v.x);
        ph[1] = __float2half_rn(v.y);
        ph[2] = __float2half_rn(v.z);
        ph[3] = __float2half_rn(v.w);
    }

    const int jj = tid & 15;
    const int rb = tid >> 4;
    const int jglob = jg * 16 + jj;
    const float b_r = __ldg(&bh[jglob]);
    const float b_z = __ldg(&bh[Hz + jglob]);
    const float b_n = __ldg(&bh[2 * Hz + jglob]);
    __syncthreads();

    // W fragment smem byte offsets (global k16 index kg selects +kg*32)
    const uint32_t w4_off = (uint32_t)(wn * 24 + (lane & 7) + ((lane >> 4) & 1) * 8) * (LDW * 2)
                            + ((lane >> 3) & 1) * 16;
    const uint32_t w2_off = (uint32_t)(wn * 24 + 16 + (lane & 7)) * (LDW * 2)
                            + ((lane >> 3) & 1) * 16;
    // h fragment addressing (256B rows: hi at +0, lo at +128; seg swizzle ^ (row&7))
    const int arow  = wm * 16 + (lane & 15);
    const int ahalf = lane >> 4;
    const uint32_t arow_off = (uint32_t)arow * 256;
    const int arow7 = arow & 7;
    // cp.async mapping: 512 threads x 2 lines = 1024 x 16B per stage
    const int prow = tid >> 3;
    const int pseg = tid & 7;
    const uint32_t pdst_off = (uint32_t)(prow * 256 + ((pseg ^ (prow & 7)) << 4));
    // gh fragment -> shg mapping
    const int frow = wm * 16 + (lane >> 2);
    const int fcol0 = wn * 24 + (lane & 3) * 2;

    for (int t = 0; t < Sz; t++) {
        if (t > 0) grid_barrier(phase_base + (unsigned)t);

        size_t prevoff, outoff;
        if (mode == 0) {
            prevoff = ((size_t)d * Sz + (size_t)(t > 0 ? t - 1 : 0)) * Bz * Hz;
            outoff  = ((size_t)d * Sz + t) * Bz * Hz;
        } else {
            int cur = t & 1;
            prevoff = ((size_t)cur * 2 + d) * Bz * Hz;
            outoff  = ((size_t)(cur ^ 1) * 2 + d) * Bz * Hz;
        }
        const __half* hphi = hhi + prevoff;
        const __half* hplo = hlo + prevoff;
        const float* gi = gi_base + (size_t)d * gi_dstride + (size_t)t * gi_tstride;

        float gir[2], giz[2], gin[2], hpv[2];
#pragma unroll
        for (int i = 0; i < 2; i++) {
            int row = rb + 32 * i;
            size_t gb = (size_t)row * gi_bstride + jglob;
            gir[i] = gi[gb];
            giz[i] = gi[gb + Hz];
            gin[i] = gi[gb + 2 * Hz];
            hpv[i] = (t > 0)
                ? __half2float(hphi[(size_t)row * Hz + jglob])
                  + __half2float(hplo[(size_t)row * Hz + jglob])
                : 0.f;
        }

        if (t > 0) {
            float acc[3][4];
#pragma unroll
            for (int nt = 0; nt < 3; nt++)
#pragma unroll
                for (int e = 0; e < 4; e++) acc[nt][e] = 0.f;

#define HCP(cc, stg) do {                                                     \
            int kt_ = (cc) * 64;                                              \
            uint32_t st_ = hsm + (uint32_t)(stg) * HSTAGE;                    \
            const __half* s0_ = hphi + (size_t)prow * Hz + kt_ + pseg * 8;    \
            asm volatile("cp.async.cg.shared.global [%0], [%1], 16;"          \
                         :: "r"(st_ + pdst_off), "l"(s0_));                   \
            const __half* s1_ = hplo + (size_t)prow * Hz + kt_ + pseg * 8;    \
            asm volatile("cp.async.cg.shared.global [%0], [%1], 16;"          \
                         :: "r"(st_ + pdst_off + 128), "l"(s1_));             \
            asm volatile("cp.async.commit_group;" ::: "memory");              \
        } while (0)

            HCP(0, 0);
            HCP(1, 1);

            const int NCH = Hz / 64;  // 16 chunks
            for (int c = 0; c < NCH; c++) {
                if (c + 1 < NCH)
                    asm volatile("cp.async.wait_group 1;" ::: "memory");
                else
                    asm volatile("cp.async.wait_group 0;" ::: "memory");
                __syncthreads();
                if (c + 2 < NCH) HCP(c + 2, (c + 2) % NSTG);

                const uint32_t hb = hsm + (uint32_t)(c % NSTG) * HSTAGE;
#pragma unroll
                for (int kk = 0; kk < 2; kk++) {
                    const int g  = wk * 2 + kk;         // k16 index within chunk
                    const int kg = c * 4 + g;           // global k16 index
                    const uint32_t sega = (uint32_t)(2 * g + ahalf);
                    uint32_t ahi[4], alo[4], wh4[4], wh2[2];
                    ldm_x4(ahi, hb + arow_off + ((sega ^ arow7) << 4));
                    ldm_x4(alo, hb + arow_off + 128 + ((sega ^ arow7) << 4));
                    ldm_x4(wh4, wsms + w4_off + (uint32_t)kg * 32);
                    ldm_x2(wh2, wsms + w2_off + (uint32_t)kg * 32);
                    mma_f16(acc[0], ahi, &wh4[0]);
                    mma_f16(acc[1], ahi, &wh4[2]);
                    mma_f16(acc[2], ahi, wh2);
                    mma_f16(acc[0], alo, &wh4[0]);
                    mma_f16(acc[1], alo, &wh4[2]);
                    mma_f16(acc[2], alo, wh2);
                }
            }
#undef HCP
            __syncthreads();   // all MMA done before shg overwrites stage smem

            if (wk == 0) {
#pragma unroll
                for (int nt = 0; nt < 3; nt++) {
                    int sc = fcol0 + nt * 8;
                    shg[sc * 65 + frow]           = acc[nt][0];
                    shg[(sc + 1) * 65 + frow]     = acc[nt][1];
                    shg[sc * 65 + frow + 8]       = acc[nt][2];
                    shg[(sc + 1) * 65 + frow + 8] = acc[nt][3];
                }
            }
            __syncthreads();
            if (wk == 1) {
#pragma unroll
                for (int nt = 0; nt < 3; nt++) {
                    int sc = fcol0 + nt * 8;
                    shg[sc * 65 + frow]           += acc[nt][0];
                    shg[(sc + 1) * 65 + frow]     += acc[nt][1];
                    shg[sc * 65 + frow + 8]       += acc[nt][2];
                    shg[(sc + 1) * 65 + frow + 8] += acc[nt][3];
                }
            }
        } else {
            for (int f = tid; f < 48 * 65; f += RTHREADS) shg[f] = 0.f;
        }
        __syncthreads();

        // pointwise GRU epilogue (2 rows per thread)
#pragma unroll
        for (int i = 0; i < 2; i++) {
            int row = rb + 32 * i;
            float ghr = shg[jj * 65 + row]        + b_r;
            float ghz = shg[(16 + jj) * 65 + row] + b_z;
            float ghn = shg[(32 + jj) * 65 + row] + b_n;

            float rg = 1.f / (1.f + expf(-(gir[i] + ghr)));
            float zg = 1.f / (1.f + expf(-(giz[i] + ghz)));
            float ng = tanhf(gin[i] + rg * ghn);
            float hnew = (1.f - zg) * ng + zg * hpv[i];

            __half hb16, lb16;
            split_f16(hnew, hb16, lb16);
            size_t oo = outoff + (size_t)row * Hz + jglob;
            hhi[oo] = hb16;
            hlo[oo] = lb16;
            if (mode == 1) {
                dout[((size_t)row * Sz + t) * 2048 + (size_t)d * Hz + jglob] = hnew;
                if (t == Sz - 1)
                    dout[(size_t)Bz * Sz * 2048 + (size_t)row * 2048 + (size_t)d * Hz + jglob] = hnew;
            }
        }
        __syncthreads();
    }
}

// ---------------- host launcher (graph-capturable: 8 kernel nodes) ----------------
extern "C" void kernel_launch(void* const* d_in, const int* in_sizes, int n_in,
                              void* d_out, int out_size)
{
    const float* x      = (const float*)d_in[0];
    const float* w_hh0f = (const float*)d_in[2];
    const float* b_hh0f = (const float*)d_in[4];
    const float* w_hh0b = (const float*)d_in[6];
    const float* b_hh0b = (const float*)d_in[8];
    const float* w_hh1f = (const float*)d_in[10];
    const float* b_ih1f = (const float*)d_in[11];
    const float* b_hh1f = (const float*)d_in[12];
    const float* w_hh1b = (const float*)d_in[14];
    const float* b_ih1b = (const float*)d_in[15];
    const float* b_hh1b = (const float*)d_in[16];
    float* out = (float*)d_out;

    float *gi0, *gi1, *b0;
    __half *xhi, *W0hi, *W0lo, *W1hi, *W1lo, *h0hi, *h0lo, *h1hi, *h1lo;
    cudaGetSymbolAddress((void**)&gi0,  g_gi0);
    cudaGetSymbolAddress((void**)&gi1,  g_gi1);
    cudaGetSymbolAddress((void**)&b0,   g_b0);
    cudaGetSymbolAddress((void**)&xhi,  g_xhi);
    cudaGetSymbolAddress((void**)&W0hi, g_W0hi);
    cudaGetSymbolAddress((void**)&W0lo, g_W0lo);
    cudaGetSymbolAddress((void**)&W1hi, g_W1hi);
    cudaGetSymbolAddress((void**)&W1lo, g_W1lo);
    cudaGetSymbolAddress((void**)&h0hi, g_h0hi);
    cudaGetSymbolAddress((void**)&h0lo, g_h0lo);
    cudaGetSymbolAddress((void**)&h1hi, g_h1hi);
    cudaGetSymbolAddress((void**)&h1lo, g_h1lo);

    cudaFuncSetAttribute(gru_layer_hmma,
                         cudaFuncAttributeMaxDynamicSharedMemorySize, REC_SMEM);
    cudaFuncSetAttribute(gemm_hmma4,
                         cudaFuncAttributeMaxDynamicSharedMemorySize, GEMM_SMEM_BYTES);

    // 1) prep: split/pack GEMM operands to fp16 hi/lo
    prep_w0_split<<<(G3z * INz + 255) / 256, 256>>>(
        (const float*)d_in[1], (const float*)d_in[5],
        (const float*)d_in[3], (const float*)d_in[7]);
    prep_x_split<<<(Bz * Sz * INz + 255) / 256, 256>>>(x);
    prep_w1_split<<<(G3z * Hz + 255) / 256, 256>>>(
        (const float*)d_in[9], (const float*)d_in[13]);

    // 2) gi0 = x @ [W_ih0f ; rev(W_ih0b)]^T + bias  (2-pass split-fp16)
    gemm_hmma4<<<dim3((2 * G3z) / 128, (Bz * Sz) / 128), 256, GEMM_SMEM_BYTES>>>(
        xhi, INz, W0hi, W0lo, INz, b0, gi0,
        INz, (size_t)Bz * Sz * G3z, G3z);

    // 3) layer-0 recurrence (fp16-W 2-pass HMMA, phases 1..511)
    gru_layer_hmma<<<NBLK, RTHREADS, REC_SMEM>>>(
        gi0, (size_t)Bz * Sz * G3z, (size_t)G3z, (size_t)Sz * G3z,
        w_hh0f, w_hh0b, b_hh0f, b_hh0b,
        h0hi, h0lo, 0, 0u, nullptr);

    // 4) gi1 = h0_all @ W_ih1^T + bias (2-pass split-fp16, per dir)
    for (int dir = 0; dir < 2; dir++) {
        gemm_hmma4<<<dim3(G3z / 128, (Sz * Bz) / 128), 256, GEMM_SMEM_BYTES>>>(
            h0hi + (size_t)dir * Sz * Bz * Hz, Hz,
            W1hi + (size_t)dir * G3z * Hz,
            W1lo + (size_t)dir * G3z * Hz, Hz,
            dir ? b_ih1b : b_ih1f,
            gi1 + (size_t)dir * Sz * Bz * G3z,
            Hz, (size_t)0, G3z);
    }

    // 5) layer-1 recurrence (fp16-W 2-pass HMMA, phases 512..1022), writes output
    gru_layer_hmma<<<NBLK, RTHREADS, REC_SMEM>>>(
        gi1, (size_t)Sz * Bz * G3z, (size_t)Bz * G3z, (size_t)G3z,
        w_hh1f, w_hh1b, b_hh1f, b_hh1b,
        h1hi, h1lo, 1, (unsigned)(Sz - 1), out);
}